// round 2
// baseline (speedup 1.0000x reference)
#include <cuda_runtime.h>
#include <math.h>
#include <stdint.h>

// Problem constants (fixed shapes)
#define N_NODES 100000
#define DIM     128
#define NEDGE   600000
#define NREL    5
#define NCOLS   2304          // 128(lin_skip) + 256(film_skip) + 5*(128 lins + 256 films)

// ---------------- scratch (device globals; no allocation allowed) ----------
__device__ float g_C[(size_t)N_NODES * NCOLS];   // fused node-GEMM output (~922 MB)
__device__ float g_O[(size_t)N_NODES * DIM];     // aggregated "out" (pre-GELU)
__device__ float g_Wp[128 * NCOLS];              // packed weights  [k][c]
__device__ float g_biasv[NCOLS];                 // packed bias
__device__ int   g_cnt[N_NODES * NREL];          // per (dst, relation) edge count

// ---------------- pack weights into one [128 x 2304] matrix ---------------
__global__ void pack_w_kernel(const float* __restrict__ lin_skip_w,
                              const float* __restrict__ film_skip_w,
                              const float* __restrict__ lins_w,
                              const float* __restrict__ films_w,
                              const float* __restrict__ films_b)
{
    int idx = blockIdx.x * blockDim.x + threadIdx.x;
    int total = 128 * NCOLS;
    if (idx < total) {
        int k = idx / NCOLS;
        int c = idx % NCOLS;
        float v;
        if (c < 128) {
            v = lin_skip_w[k * 128 + c];
        } else if (c < 384) {
            v = film_skip_w[k * 256 + (c - 128)];
        } else {
            int r  = (c - 384) / 384;
            int cc = (c - 384) % 384;
            if (cc < 128) v = lins_w[((size_t)r * 128 + k) * 128 + cc];
            else          v = films_w[((size_t)r * 128 + k) * 256 + (cc - 128)];
        }
        g_Wp[idx] = v;
    }
    if (idx < NCOLS) {
        float b = 0.0f;
        if (idx >= 384) {
            int r  = (idx - 384) / 384;
            int cc = (idx - 384) % 384;
            if (cc >= 128) b = films_b[r * 256 + (cc - 128)];
        }
        g_biasv[idx] = b;
    }
}

// ---------------- zero cnt -------------------------------------------------
__global__ void zero_cnt_kernel()
{
    int i = blockIdx.x * blockDim.x + threadIdx.x;
    if (i < N_NODES * NREL) g_cnt[i] = 0;
}

// ---------------- per-(dst, relation) edge counting ------------------------
// edge_index / edge_type are int32 (JAX x64 disabled downcasts int64->int32).
__global__ void cnt_kernel(const int* __restrict__ ei,
                           const int* __restrict__ et)
{
    int e = blockIdx.x * blockDim.x + threadIdx.x;
    if (e < NEDGE) {
        int dst = ei[NEDGE + e];
        int r   = et[e];
        atomicAdd(&g_cnt[dst * NREL + r], 1);
    }
}

// ---------------- generic fp32 GEMM: Cout[M, ncols] = A[M,128] @ W + bias --
// 128x128 tile, K=128, 256 threads, 8x8 per thread.
__global__ void __launch_bounds__(256)
gemm_bias_kernel(const float* __restrict__ A,
                 const float* __restrict__ W, int ldw,
                 const float* __restrict__ bias,
                 float* __restrict__ Cout, int M, int ncols_total)
{
    __shared__ float As[16][132];   // transposed A tile, padded
    __shared__ float Bs[16][128];

    int tid     = threadIdx.x;
    int rowBase = blockIdx.x * 128;
    int colBase = blockIdx.y * 128;
    int ty = tid >> 4;   // 0..15
    int tx = tid & 15;   // 0..15

    float acc[8][8];
#pragma unroll
    for (int i = 0; i < 8; ++i)
#pragma unroll
        for (int j = 0; j < 8; ++j) acc[i][j] = 0.0f;

    for (int k0 = 0; k0 < 128; k0 += 16) {
        // load A tile (128 rows x 16 k), store transposed
#pragma unroll
        for (int it = 0; it < 2; ++it) {
            int idx = tid + it * 256;          // 0..511
            int row = idx >> 2;                // 0..127
            int kq  = (idx & 3) << 2;          // 0,4,8,12
            float4 v = make_float4(0.f, 0.f, 0.f, 0.f);
            int grow = rowBase + row;
            if (grow < M)
                v = *reinterpret_cast<const float4*>(&A[(size_t)grow * 128 + k0 + kq]);
            As[kq + 0][row] = v.x;
            As[kq + 1][row] = v.y;
            As[kq + 2][row] = v.z;
            As[kq + 3][row] = v.w;
        }
        // load B tile (16 k x 128 cols)
#pragma unroll
        for (int it = 0; it < 2; ++it) {
            int idx = tid + it * 256;
            int kk  = idx >> 5;                // 0..15
            int cq  = (idx & 31) << 2;         // 0..124
            float4 v = *reinterpret_cast<const float4*>(
                &W[(size_t)(k0 + kk) * ldw + colBase + cq]);
            *reinterpret_cast<float4*>(&Bs[kk][cq]) = v;
        }
        __syncthreads();

#pragma unroll
        for (int kk = 0; kk < 16; ++kk) {
            float a[8], b[8];
#pragma unroll
            for (int i = 0; i < 8; ++i) a[i] = As[kk][ty * 8 + i];
#pragma unroll
            for (int j = 0; j < 8; ++j) b[j] = Bs[kk][tx * 8 + j];
#pragma unroll
            for (int i = 0; i < 8; ++i)
#pragma unroll
                for (int j = 0; j < 8; ++j)
                    acc[i][j] = fmaf(a[i], b[j], acc[i][j]);
        }
        __syncthreads();
    }

    // epilogue: add bias, store
#pragma unroll
    for (int i = 0; i < 8; ++i) {
        int grow = rowBase + ty * 8 + i;
        if (grow >= M) continue;
#pragma unroll
        for (int j = 0; j < 8; j += 4) {
            int gc = colBase + tx * 8 + j;
            float4 v;
            v.x = acc[i][j + 0] + bias[gc + 0];
            v.y = acc[i][j + 1] + bias[gc + 1];
            v.z = acc[i][j + 2] + bias[gc + 2];
            v.w = acc[i][j + 3] + bias[gc + 3];
            *reinterpret_cast<float4*>(&Cout[(size_t)grow * ncols_total + gc]) = v;
        }
    }
}

// ---------------- skip/FiLM init: O = relu(gamma_s * lin + beta_s) --------
__global__ void skip_init_kernel()
{
    int i = blockIdx.x * blockDim.x + threadIdx.x;   // over N*32 float4s
    int total = N_NODES * 32;
    if (i >= total) return;
    int row = i >> 5;
    int q   = (i & 31) << 2;
    const float* base = &g_C[(size_t)row * NCOLS];
    float4 lin   = *reinterpret_cast<const float4*>(&base[q]);
    float4 beta  = *reinterpret_cast<const float4*>(&base[128 + q]);
    float4 gamma = *reinterpret_cast<const float4*>(&base[256 + q]);
    float4 o;
    o.x = fmaxf(gamma.x * lin.x + beta.x, 0.0f);
    o.y = fmaxf(gamma.y * lin.y + beta.y, 0.0f);
    o.z = fmaxf(gamma.z * lin.z + beta.z, 0.0f);
    o.w = fmaxf(gamma.w * lin.w + beta.w, 0.0f);
    *reinterpret_cast<float4*>(&g_O[(size_t)row * 128 + q]) = o;
}

// ---------------- edge message pass: one warp per edge ---------------------
__global__ void edge_kernel(const int* __restrict__ ei,
                            const int* __restrict__ et)
{
    int gthread = blockIdx.x * blockDim.x + threadIdx.x;
    int warp = gthread >> 5;
    int lane = gthread & 31;
    if (warp >= NEDGE) return;

    int src = ei[warp];
    int dst = ei[NEDGE + warp];
    int r   = et[warp];

    const float* xl = &g_C[(size_t)src * NCOLS + 384 + r * 384];
    const float* bg = &g_C[(size_t)dst * NCOLS + 384 + r * 384 + 128];
    int c = g_cnt[dst * NREL + r];
    float inv = 1.0f / (float)(c > 0 ? c : 1);
    float* o = &g_O[(size_t)dst * 128];

    int j = lane << 2;   // 4 floats per lane covers 128
    float4 x4 = *reinterpret_cast<const float4*>(&xl[j]);
    float4 b4 = *reinterpret_cast<const float4*>(&bg[j]);
    float4 gmm = *reinterpret_cast<const float4*>(&bg[128 + j]);
    float v0 = fmaxf(gmm.x * x4.x + b4.x, 0.0f) * inv;
    float v1 = fmaxf(gmm.y * x4.y + b4.y, 0.0f) * inv;
    float v2 = fmaxf(gmm.z * x4.z + b4.z, 0.0f) * inv;
    float v3 = fmaxf(gmm.w * x4.w + b4.w, 0.0f) * inv;
    atomicAdd(&o[j + 0], v0);
    atomicAdd(&o[j + 1], v1);
    atomicAdd(&o[j + 2], v2);
    atomicAdd(&o[j + 3], v3);
}

// ---------------- exact GELU (erf) in-place on g_O --------------------------
__global__ void gelu_kernel()
{
    int i = blockIdx.x * blockDim.x + threadIdx.x;
    int total = (N_NODES * DIM) / 4;
    if (i >= total) return;
    float4 v = reinterpret_cast<float4*>(g_O)[i];
    const float k = 0.70710678118654752f;
    v.x = 0.5f * v.x * (1.0f + erff(v.x * k));
    v.y = 0.5f * v.y * (1.0f + erff(v.y * k));
    v.z = 0.5f * v.z * (1.0f + erff(v.z * k));
    v.w = 0.5f * v.w * (1.0f + erff(v.w * k));
    reinterpret_cast<float4*>(g_O)[i] = v;
}

// ---------------- launch ----------------------------------------------------
extern "C" void kernel_launch(void* const* d_in, const int* in_sizes, int n_in,
                              void* d_out, int out_size)
{
    const float* x           = (const float*)d_in[0];
    const int*   ei          = (const int*)d_in[1];
    const int*   et          = (const int*)d_in[2];
    const float* lin_skip_w  = (const float*)d_in[3];
    const float* film_skip_w = (const float*)d_in[4];
    const float* lins_w      = (const float*)d_in[5];
    const float* films_w     = (const float*)d_in[6];
    const float* films_b     = (const float*)d_in[7];
    const float* linear1_w   = (const float*)d_in[8];
    const float* linear1_b   = (const float*)d_in[9];
    float*       out         = (float*)d_out;

    void *pC, *pO, *pWp, *pBias;
    cudaGetSymbolAddress(&pC, g_C);
    cudaGetSymbolAddress(&pO, g_O);
    cudaGetSymbolAddress(&pWp, g_Wp);
    cudaGetSymbolAddress(&pBias, g_biasv);

    // 1. pack weights + bias
    {
        int total = 128 * NCOLS;
        pack_w_kernel<<<(total + 255) / 256, 256>>>(lin_skip_w, film_skip_w,
                                                    lins_w, films_w, films_b);
    }
    // 2. zero counts, count edges per (dst, relation)
    zero_cnt_kernel<<<(N_NODES * NREL + 255) / 256, 256>>>();
    cnt_kernel<<<(NEDGE + 255) / 256, 256>>>(ei, et);

    // 3. fused node GEMM: C[N, 2304] = x @ Wpack + bias
    {
        dim3 grid((N_NODES + 127) / 128, NCOLS / 128);
        gemm_bias_kernel<<<grid, 256>>>(x, (const float*)pWp, NCOLS,
                                        (const float*)pBias, (float*)pC,
                                        N_NODES, NCOLS);
    }

    // 4. skip/FiLM init of O
    skip_init_kernel<<<(N_NODES * 32 + 255) / 256, 256>>>();

    // 5. edge message pass (one warp per edge)
    {
        int threads = 256;
        int warps_per_block = threads / 32;
        int blocks = (NEDGE + warps_per_block - 1) / warps_per_block;
        edge_kernel<<<blocks, threads>>>(ei, et);
    }

    // 6. exact GELU in-place
    gelu_kernel<<<(N_NODES * DIM / 4 + 255) / 256, 256>>>();

    // 7. final GEMM: out = gelu(O) @ linear1_w + linear1_b
    {
        dim3 grid((N_NODES + 127) / 128, 1);
        gemm_bias_kernel<<<grid, 256>>>((const float*)pO, linear1_w, 128,
                                        linear1_b, out, N_NODES, 128);
    }
}

// round 5
// speedup vs baseline: 1.2285x; 1.2285x over previous
#include <cuda_runtime.h>
#include <cuda_bf16.h>
#include <math.h>
#include <stdint.h>

// Problem constants (fixed shapes)
#define N_NODES 100000
#define DIM     128
#define NEDGE   600000
#define NREL    5
#define NCOLS   2304          // 128 lin_skip + 256 film_skip + 5*(128 lins + 256 films)
#define NCOLSW  2432          // + 128 cols for linear1_w (final projection)

// ---------------- scratch (device globals; no allocation allowed) ----------
__device__ float         g_C[(size_t)N_NODES * NCOLS]; // fused node-GEMM output
__device__ float         g_O[(size_t)N_NODES * DIM];   // aggregated "out" (pre-GELU)
__device__ __nv_bfloat16 g_xhi[(size_t)N_NODES * DIM]; // A hi (x, later gelu(out))
__device__ __nv_bfloat16 g_xlo[(size_t)N_NODES * DIM]; // A lo
__device__ __nv_bfloat16 g_Wthi[(size_t)NCOLSW * DIM]; // W^T hi: [c][k]
__device__ __nv_bfloat16 g_Wtlo[(size_t)NCOLSW * DIM]; // W^T lo
__device__ float         g_biasv[NCOLSW];              // packed bias
__device__ int           g_cnt[N_NODES * NREL];        // per (dst, rel) edge count

// ---------------- PTX helpers (base PTX only; no 'a' features) -------------
__device__ __forceinline__ uint32_t smem_u32(const void* p) {
    uint32_t a;
    asm("{ .reg .u64 t; cvta.to.shared.u64 t, %1; cvt.u32.u64 %0, t; }"
        : "=r"(a) : "l"(p));
    return a;
}

__device__ __forceinline__ void ldsm_x4(uint32_t (&r)[4], uint32_t addr) {
    asm volatile("ldmatrix.sync.aligned.m8n8.x4.shared.b16 {%0,%1,%2,%3}, [%4];"
                 : "=r"(r[0]), "=r"(r[1]), "=r"(r[2]), "=r"(r[3]) : "r"(addr));
}
__device__ __forceinline__ void mma16816(float (&d)[4], const uint32_t (&a)[4],
                                         const uint32_t (&b)[2]) {
    asm volatile(
        "mma.sync.aligned.m16n8k16.row.col.f32.bf16.bf16.f32 "
        "{%0,%1,%2,%3}, {%4,%5,%6,%7}, {%8,%9}, {%0,%1,%2,%3};"
        : "+f"(d[0]), "+f"(d[1]), "+f"(d[2]), "+f"(d[3])
        : "r"(a[0]), "r"(a[1]), "r"(a[2]), "r"(a[3]), "r"(b[0]), "r"(b[1]));
}

// ---------------- prep kernels ----------------------------------------------
__global__ void split_x_kernel(const float* __restrict__ x)
{
    int i = blockIdx.x * blockDim.x + threadIdx.x;
    if (i >= N_NODES * DIM) return;
    float v  = x[i];
    __nv_bfloat16 hi = __float2bfloat16(v);
    __nv_bfloat16 lo = __float2bfloat16(v - __bfloat162float(hi));
    g_xhi[i] = hi;
    g_xlo[i] = lo;
}

__global__ void pack_wt_kernel(const float* __restrict__ lin_skip_w,
                               const float* __restrict__ film_skip_w,
                               const float* __restrict__ lins_w,
                               const float* __restrict__ films_w,
                               const float* __restrict__ films_b,
                               const float* __restrict__ linear1_w,
                               const float* __restrict__ linear1_b)
{
    int idx = blockIdx.x * blockDim.x + threadIdx.x;   // over NCOLSW*128
    if (idx < NCOLSW * DIM) {
        int c = idx / DIM;
        int k = idx % DIM;
        float v;
        if (c < 128) {
            v = lin_skip_w[k * 128 + c];
        } else if (c < 384) {
            v = film_skip_w[k * 256 + (c - 128)];
        } else if (c < NCOLS) {
            int r  = (c - 384) / 384;
            int cc = (c - 384) % 384;
            if (cc < 128) v = lins_w[((size_t)r * 128 + k) * 128 + cc];
            else          v = films_w[((size_t)r * 128 + k) * 256 + (cc - 128)];
        } else {
            v = linear1_w[k * 128 + (c - NCOLS)];
        }
        __nv_bfloat16 hi = __float2bfloat16(v);
        __nv_bfloat16 lo = __float2bfloat16(v - __bfloat162float(hi));
        g_Wthi[idx] = hi;
        g_Wtlo[idx] = lo;
    }
    if (idx < NCOLSW) {
        float b = 0.0f;
        if (idx >= 384 && idx < NCOLS) {
            int r  = (idx - 384) / 384;
            int cc = (idx - 384) % 384;
            if (cc >= 128) b = films_b[r * 256 + (cc - 128)];
        } else if (idx >= NCOLS) {
            b = linear1_b[idx - NCOLS];
        }
        g_biasv[idx] = b;
    }
}

__global__ void zero_cnt_kernel()
{
    int i = blockIdx.x * blockDim.x + threadIdx.x;
    if (i < N_NODES * NREL) g_cnt[i] = 0;
}

__global__ void cnt_kernel(const int* __restrict__ ei, const int* __restrict__ et)
{
    int e = blockIdx.x * blockDim.x + threadIdx.x;
    if (e < NEDGE) {
        int dst = ei[NEDGE + e];
        int r   = et[e];
        atomicAdd(&g_cnt[dst * NREL + r], 1);
    }
}

// ---------------- mma.sync GEMM (bf16 hi/lo 3-pass, legacy HMMA path) -------
// C[128 x TN] tile per CTA; whole K=128 resident in SMEM.
// Both A [m][k] and B=W^T [n][k] are k-major -> BOTH use non-trans ldmatrix.
#define RSTRIDE 272

template <int TN>
__global__ void __launch_bounds__(256, 1)
mma_gemm_kernel(const __nv_bfloat16* __restrict__ Ahi,
                const __nv_bfloat16* __restrict__ Alo,
                const __nv_bfloat16* __restrict__ Whi,
                const __nv_bfloat16* __restrict__ Wlo,
                const float* __restrict__ bias,
                float* __restrict__ Cout, int ldc,
                int colBase0, int M)
{
    constexpr int NF = TN / 32;   // n-fragments per warp (warp tile = 64 x TN/4)
    extern __shared__ char smem[];
    uint32_t sb = smem_u32(smem);

    int tid  = threadIdx.x;
    int wid  = tid >> 5;
    int lane = tid & 31;
    int rowBase = blockIdx.x * 128;
    int colBase = colBase0 + blockIdx.y * TN;

    const uint32_t sAlo = 128 * RSTRIDE;          // 34816
    const uint32_t sB   = 2 * 128 * RSTRIDE;      // 69632
    const uint32_t sBsz = (uint32_t)TN * RSTRIDE;

    // ---- stage A (hi+lo) ----
    for (int i = tid; i < 128 * 16; i += 256) {
        int row = i >> 4, ch = i & 15;
        int grow = rowBase + row;
        uint4 vh = make_uint4(0, 0, 0, 0), vl = vh;
        if (grow < M) {
            vh = *(const uint4*)(Ahi + (size_t)grow * DIM + ch * 8);
            vl = *(const uint4*)(Alo + (size_t)grow * DIM + ch * 8);
        }
        *(uint4*)(smem + row * RSTRIDE + ch * 16)        = vh;
        *(uint4*)(smem + sAlo + row * RSTRIDE + ch * 16) = vl;
    }
    // ---- stage B (hi+lo) ----
    for (int i = tid; i < TN * 16; i += 256) {
        int row = i >> 4, ch = i & 15;
        int gc = colBase + row;
        *(uint4*)(smem + sB + row * RSTRIDE + ch * 16) =
            *(const uint4*)(Whi + (size_t)gc * DIM + ch * 8);
        *(uint4*)(smem + sB + sBsz + row * RSTRIDE + ch * 16) =
            *(const uint4*)(Wlo + (size_t)gc * DIM + ch * 8);
    }
    __syncthreads();

    int mBase = (wid >> 2) * 64;
    int nBase = (wid & 3) * (TN / 4);

    float acc[4][NF][4];
#pragma unroll
    for (int i = 0; i < 4; ++i)
#pragma unroll
        for (int j = 0; j < NF; ++j)
#pragma unroll
            for (int q = 0; q < 4; ++q) acc[i][j][q] = 0.0f;

    // ldmatrix base addresses (per-lane)
    // A: lanes0-7 rows0-7/k0-7, 8-15 rows8-15/k0-7, 16-23 rows0-7/k8-15, 24-31 rows8-15/k8-15
    uint32_t aAddr = sb + (uint32_t)(mBase + (lane & 15)) * RSTRIDE
                   + (uint32_t)((lane >> 4) << 3) * 2;
    // B (non-trans): lanes0-7 n0-7/k0-7 (b0 of n-block0), 8-15 n0-7/k8-15 (b1),
    //                16-23 n8-15/k0-7 (b0 of n-block1), 24-31 n8-15/k8-15 (b1)
    uint32_t bAddr = sb + sB
                   + (uint32_t)(nBase + (((lane >> 4) & 1) << 3) + (lane & 7)) * RSTRIDE
                   + (uint32_t)(((lane >> 3) & 1) << 3) * 2;

#pragma unroll
    for (int p = 0; p < 3; ++p) {           // hi*hi, hi*lo, lo*hi
        uint32_t aOff = (p < 2) ? 0u : sAlo;
        uint32_t bOff = (p == 1) ? sBsz : 0u;
#pragma unroll
        for (int ks = 0; ks < 8; ++ks) {
            uint32_t a[4][4];
#pragma unroll
            for (int i = 0; i < 4; ++i)
                ldsm_x4(a[i], aAddr + aOff + i * 16 * RSTRIDE + ks * 32);
            uint32_t b[NF][2];
#pragma unroll
            for (int jj = 0; jj < NF / 2; ++jj) {
                uint32_t r[4];
                ldsm_x4(r, bAddr + bOff + jj * 16 * RSTRIDE + ks * 32);
                b[2 * jj][0] = r[0]; b[2 * jj][1] = r[1];
                b[2 * jj + 1][0] = r[2]; b[2 * jj + 1][1] = r[3];
            }
#pragma unroll
            for (int i = 0; i < 4; ++i)
#pragma unroll
                for (int j = 0; j < NF; ++j)
                    mma16816(acc[i][j], a[i], b[j]);
        }
    }

    // ---- epilogue: add bias, store ----
    int outColBase = colBase - colBase0;
#pragma unroll
    for (int i = 0; i < 4; ++i) {
        int row0 = rowBase + mBase + i * 16 + (lane >> 2);
#pragma unroll
        for (int h = 0; h < 2; ++h) {
            int grow = row0 + h * 8;
            if (grow >= M) continue;
            float* crow = Cout + (size_t)grow * ldc + outColBase;
#pragma unroll
            for (int j = 0; j < NF; ++j) {
                int c = nBase + j * 8 + ((lane & 3) << 1);
                float2 v;
                v.x = acc[i][j][h * 2 + 0] + bias[colBase + c];
                v.y = acc[i][j][h * 2 + 1] + bias[colBase + c + 1];
                *(float2*)(crow + c) = v;
            }
        }
    }
}

// ---------------- skip/FiLM init: O = relu(gamma_s * lin + beta_s) ---------
__global__ void skip_init_kernel()
{
    int i = blockIdx.x * blockDim.x + threadIdx.x;
    int total = N_NODES * 32;
    if (i >= total) return;
    int row = i >> 5;
    int q   = (i & 31) << 2;
    const float* base = &g_C[(size_t)row * NCOLS];
    float4 lin   = *reinterpret_cast<const float4*>(&base[q]);
    float4 beta  = *reinterpret_cast<const float4*>(&base[128 + q]);
    float4 gamma = *reinterpret_cast<const float4*>(&base[256 + q]);
    float4 o;
    o.x = fmaxf(gamma.x * lin.x + beta.x, 0.0f);
    o.y = fmaxf(gamma.y * lin.y + beta.y, 0.0f);
    o.z = fmaxf(gamma.z * lin.z + beta.z, 0.0f);
    o.w = fmaxf(gamma.w * lin.w + beta.w, 0.0f);
    *reinterpret_cast<float4*>(&g_O[(size_t)row * 128 + q]) = o;
}

// ---------------- edge message pass: one warp per edge ----------------------
__global__ void edge_kernel(const int* __restrict__ ei, const int* __restrict__ et)
{
    int gthread = blockIdx.x * blockDim.x + threadIdx.x;
    int warp = gthread >> 5;
    int lane = gthread & 31;
    if (warp >= NEDGE) return;

    int src = ei[warp];
    int dst = ei[NEDGE + warp];
    int r   = et[warp];

    const float* xl = &g_C[(size_t)src * NCOLS + 384 + r * 384];
    const float* bg = &g_C[(size_t)dst * NCOLS + 384 + r * 384 + 128];
    int c = g_cnt[dst * NREL + r];
    float inv = 1.0f / (float)(c > 0 ? c : 1);
    float* o = &g_O[(size_t)dst * 128];

    int j = lane << 2;
    float4 x4  = *reinterpret_cast<const float4*>(&xl[j]);
    float4 b4  = *reinterpret_cast<const float4*>(&bg[j]);
    float4 gmm = *reinterpret_cast<const float4*>(&bg[128 + j]);
    float v0 = fmaxf(gmm.x * x4.x + b4.x, 0.0f) * inv;
    float v1 = fmaxf(gmm.y * x4.y + b4.y, 0.0f) * inv;
    float v2 = fmaxf(gmm.z * x4.z + b4.z, 0.0f) * inv;
    float v3 = fmaxf(gmm.w * x4.w + b4.w, 0.0f) * inv;
    atomicAdd(&o[j + 0], v0);
    atomicAdd(&o[j + 1], v1);
    atomicAdd(&o[j + 2], v2);
    atomicAdd(&o[j + 3], v3);
}

// ---------------- exact GELU + bf16 hi/lo split for final projection -------
__global__ void gelu_split_kernel()
{
    int i = blockIdx.x * blockDim.x + threadIdx.x;
    if (i >= N_NODES * DIM) return;
    float v = g_O[i];
    float g = 0.5f * v * (1.0f + erff(v * 0.70710678118654752f));
    __nv_bfloat16 hi = __float2bfloat16(g);
    __nv_bfloat16 lo = __float2bfloat16(g - __bfloat162float(hi));
    g_xhi[i] = hi;
    g_xlo[i] = lo;
}

// ---------------- launch ------------------------------------------------------
extern "C" void kernel_launch(void* const* d_in, const int* in_sizes, int n_in,
                              void* d_out, int out_size)
{
    const float* x           = (const float*)d_in[0];
    const int*   ei          = (const int*)d_in[1];
    const int*   et          = (const int*)d_in[2];
    const float* lin_skip_w  = (const float*)d_in[3];
    const float* film_skip_w = (const float*)d_in[4];
    const float* lins_w      = (const float*)d_in[5];
    const float* films_w     = (const float*)d_in[6];
    const float* films_b     = (const float*)d_in[7];
    const float* linear1_w   = (const float*)d_in[8];
    const float* linear1_b   = (const float*)d_in[9];
    float*       out         = (float*)d_out;

    void *pC, *pXhi, *pXlo, *pWhi, *pWlo, *pBias;
    cudaGetSymbolAddress(&pC,   g_C);
    cudaGetSymbolAddress(&pXhi, g_xhi);
    cudaGetSymbolAddress(&pXlo, g_xlo);
    cudaGetSymbolAddress(&pWhi, g_Wthi);
    cudaGetSymbolAddress(&pWlo, g_Wtlo);
    cudaGetSymbolAddress(&pBias, g_biasv);

    const int SMEM_MAIN = 2 * 128 * RSTRIDE + 2 * 256 * RSTRIDE;  // 208896
    const int SMEM_FIN  = 2 * 128 * RSTRIDE + 2 * 128 * RSTRIDE;  // 139264
    cudaFuncSetAttribute(mma_gemm_kernel<256>,
                         cudaFuncAttributeMaxDynamicSharedMemorySize, SMEM_MAIN);
    cudaFuncSetAttribute(mma_gemm_kernel<128>,
                         cudaFuncAttributeMaxDynamicSharedMemorySize, SMEM_FIN);

    // 1. prep: split x, pack W^T hi/lo + bias (incl. linear1)
    split_x_kernel<<<(N_NODES * DIM + 255) / 256, 256>>>(x);
    pack_wt_kernel<<<(NCOLSW * DIM + 255) / 256, 256>>>(
        lin_skip_w, film_skip_w, lins_w, films_w, films_b, linear1_w, linear1_b);

    // 2. zero counts, count edges per (dst, relation)
    zero_cnt_kernel<<<(N_NODES * NREL + 255) / 256, 256>>>();
    cnt_kernel<<<(NEDGE + 255) / 256, 256>>>(ei, et);

    // 3. fused node GEMM (HMMA): C[N, 2304] = x @ Wpack + bias
    {
        dim3 grid((N_NODES + 127) / 128, NCOLS / 256);
        mma_gemm_kernel<256><<<grid, 256, SMEM_MAIN>>>(
            (const __nv_bfloat16*)pXhi, (const __nv_bfloat16*)pXlo,
            (const __nv_bfloat16*)pWhi, (const __nv_bfloat16*)pWlo,
            (const float*)pBias, (float*)pC, NCOLS, 0, N_NODES);
    }

    // 4. skip/FiLM init of O
    skip_init_kernel<<<(N_NODES * 32 + 255) / 256, 256>>>();

    // 5. edge message pass (one warp per edge)
    {
        int threads = 256;
        int wpb = threads / 32;
        int blocks = (NEDGE + wpb - 1) / wpb;
        edge_kernel<<<blocks, threads>>>(ei, et);
    }

    // 6. exact GELU + split to bf16 hi/lo
    gelu_split_kernel<<<(N_NODES * DIM + 255) / 256, 256>>>();

    // 7. final projection (HMMA): out = gelu(O) @ linear1_w + linear1_b
    {
        dim3 grid((N_NODES + 127) / 128, 1);
        mma_gemm_kernel<128><<<grid, 256, SMEM_FIN>>>(
            (const __nv_bfloat16*)pXhi, (const __nv_bfloat16*)pXlo,
            (const __nv_bfloat16*)pWhi, (const __nv_bfloat16*)pWlo,
            (const float*)pBias, out, 128, NCOLS, N_NODES);
    }
}

// round 6
// speedup vs baseline: 1.5777x; 1.2842x over previous
#include <cuda_runtime.h>
#include <cuda_fp16.h>
#include <math.h>
#include <stdint.h>

// Problem constants (fixed shapes)
#define N_NODES 100000
#define DIM     128
#define NEDGE   600000
#define NREL    5
#define NCOLS   2304          // 128 lin_skip + 256 film_skip + 5*(128 lins + 256 films)
#define NCOLSW  2432          // + 128 cols for linear1_w (final projection)

// ---------------- scratch (device globals; no allocation allowed) ----------
__device__ float  g_C[(size_t)N_NODES * NCOLS]; // fused node-GEMM output
__device__ float  g_O[(size_t)N_NODES * DIM];   // aggregated "out" (pre-GELU)
__device__ __half g_Wh[(size_t)NCOLSW * DIM];   // W^T fp16: [c][k]
__device__ float  g_biasv[NCOLSW];              // packed bias
__device__ int    g_cnt[N_NODES * NREL];        // per (dst, rel) edge count

// ---------------- PTX helpers (base PTX only; no 'a' features) -------------
__device__ __forceinline__ uint32_t smem_u32(const void* p) {
    uint32_t a;
    asm("{ .reg .u64 t; cvta.to.shared.u64 t, %1; cvt.u32.u64 %0, t; }"
        : "=r"(a) : "l"(p));
    return a;
}

__device__ __forceinline__ void ldsm_x4(uint32_t (&r)[4], uint32_t addr) {
    asm volatile("ldmatrix.sync.aligned.m8n8.x4.shared.b16 {%0,%1,%2,%3}, [%4];"
                 : "=r"(r[0]), "=r"(r[1]), "=r"(r[2]), "=r"(r[3]) : "r"(addr));
}
__device__ __forceinline__ void mma16816(float (&d)[4], const uint32_t (&a)[4],
                                         const uint32_t (&b)[2]) {
    asm volatile(
        "mma.sync.aligned.m16n8k16.row.col.f32.f16.f16.f32 "
        "{%0,%1,%2,%3}, {%4,%5,%6,%7}, {%8,%9}, {%0,%1,%2,%3};"
        : "+f"(d[0]), "+f"(d[1]), "+f"(d[2]), "+f"(d[3])
        : "r"(a[0]), "r"(a[1]), "r"(a[2]), "r"(a[3]), "r"(b[0]), "r"(b[1]));
}

__device__ __forceinline__ uint32_t pack2h(__half a, __half b) {
    __half2 t = __halves2half2(a, b);
    return *reinterpret_cast<uint32_t*>(&t);
}

// ---------------- prep kernels ----------------------------------------------
__global__ void pack_wt_kernel(const float* __restrict__ lin_skip_w,
                               const float* __restrict__ film_skip_w,
                               const float* __restrict__ lins_w,
                               const float* __restrict__ films_w,
                               const float* __restrict__ films_b,
                               const float* __restrict__ linear1_w,
                               const float* __restrict__ linear1_b)
{
    int idx = blockIdx.x * blockDim.x + threadIdx.x;   // over NCOLSW*128
    if (idx < NCOLSW * DIM) {
        int c = idx / DIM;
        int k = idx % DIM;
        float v;
        if (c < 128) {
            v = lin_skip_w[k * 128 + c];
        } else if (c < 384) {
            v = film_skip_w[k * 256 + (c - 128)];
        } else if (c < NCOLS) {
            int r  = (c - 384) / 384;
            int cc = (c - 384) % 384;
            if (cc < 128) v = lins_w[((size_t)r * 128 + k) * 128 + cc];
            else          v = films_w[((size_t)r * 128 + k) * 256 + (cc - 128)];
        } else {
            v = linear1_w[k * 128 + (c - NCOLS)];
        }
        g_Wh[idx] = __float2half_rn(v);
    }
    if (idx < NCOLSW) {
        float b = 0.0f;
        if (idx >= 384 && idx < NCOLS) {
            int r  = (idx - 384) / 384;
            int cc = (idx - 384) % 384;
            if (cc >= 128) b = films_b[r * 256 + (cc - 128)];
        } else if (idx >= NCOLS) {
            b = linear1_b[idx - NCOLS];
        }
        g_biasv[idx] = b;
    }
}

__global__ void zero_cnt_kernel()
{
    int i = blockIdx.x * blockDim.x + threadIdx.x;
    if (i < N_NODES * NREL) g_cnt[i] = 0;
}

__global__ void cnt_kernel(const int* __restrict__ ei, const int* __restrict__ et)
{
    int e = blockIdx.x * blockDim.x + threadIdx.x;
    if (e < NEDGE) {
        int dst = ei[NEDGE + e];
        int r   = et[e];
        atomicAdd(&g_cnt[dst * NREL + r], 1);
    }
}

// ---------------- mma.sync GEMM (fp16 A-split hi/lo, 2 passes) --------------
// C[128 x TN] tile per CTA; whole K=128 resident in SMEM.
// A source is fp32; split to fp16 hi/lo in the staging loop (optional GELU).
// B = W^T [n][k] fp16 (single precision level; rounding of W is the only
// approximation: u = 2^-11 -> rel err ~1e-4).
#define RSTRIDE 272

template <int TN, bool GELU>
__global__ void __launch_bounds__(256, 1)
mma_gemm_kernel(const float* __restrict__ A,
                const __half* __restrict__ W,
                const float* __restrict__ bias,
                float* __restrict__ Cout, int ldc,
                int colBase0, int M)
{
    constexpr int NF = TN / 32;   // n-fragments per warp (warp tile = 64 x TN/4)
    extern __shared__ char smem[];
    uint32_t sb = smem_u32(smem);

    int tid  = threadIdx.x;
    int wid  = tid >> 5;
    int lane = tid & 31;
    int rowBase = blockIdx.x * 128;
    int colBase = colBase0 + blockIdx.y * TN;

    const uint32_t sAlo = 128 * RSTRIDE;          // 34816
    const uint32_t sB   = 2 * 128 * RSTRIDE;      // 69632

    // ---- stage A: read fp32, (optional gelu), split to fp16 hi/lo ----
    for (int i = tid; i < 128 * 16; i += 256) {
        int row = i >> 4, ch = i & 15;            // ch indexes 8-float chunks
        int grow = rowBase + row;
        float v[8];
        if (grow < M) {
            float4 f0 = *(const float4*)(A + (size_t)grow * DIM + ch * 8);
            float4 f1 = *(const float4*)(A + (size_t)grow * DIM + ch * 8 + 4);
            v[0]=f0.x; v[1]=f0.y; v[2]=f0.z; v[3]=f0.w;
            v[4]=f1.x; v[5]=f1.y; v[6]=f1.z; v[7]=f1.w;
        } else {
#pragma unroll
            for (int j = 0; j < 8; ++j) v[j] = 0.0f;
        }
        if (GELU) {
#pragma unroll
            for (int j = 0; j < 8; ++j)
                v[j] = 0.5f * v[j] * (1.0f + erff(v[j] * 0.70710678118654752f));
        }
        __half h[8], l[8];
#pragma unroll
        for (int j = 0; j < 8; ++j) {
            h[j] = __float2half_rn(v[j]);
            l[j] = __float2half_rn(v[j] - __half2float(h[j]));
        }
        uint4 uh, ul;
        uh.x = pack2h(h[0], h[1]); uh.y = pack2h(h[2], h[3]);
        uh.z = pack2h(h[4], h[5]); uh.w = pack2h(h[6], h[7]);
        ul.x = pack2h(l[0], l[1]); ul.y = pack2h(l[2], l[3]);
        ul.z = pack2h(l[4], l[5]); ul.w = pack2h(l[6], l[7]);
        *(uint4*)(smem + row * RSTRIDE + ch * 16)        = uh;
        *(uint4*)(smem + sAlo + row * RSTRIDE + ch * 16) = ul;
    }
    // ---- stage B (fp16 W^T rows) ----
    for (int i = tid; i < TN * 16; i += 256) {
        int row = i >> 4, ch = i & 15;
        int gc = colBase + row;
        *(uint4*)(smem + sB + row * RSTRIDE + ch * 16) =
            *(const uint4*)(W + (size_t)gc * DIM + ch * 8);
    }
    __syncthreads();

    int mBase = (wid >> 2) * 64;
    int nBase = (wid & 3) * (TN / 4);

    float acc[4][NF][4];
#pragma unroll
    for (int i = 0; i < 4; ++i)
#pragma unroll
        for (int j = 0; j < NF; ++j)
#pragma unroll
            for (int q = 0; q < 4; ++q) acc[i][j][q] = 0.0f;

    // ldmatrix base addresses (per-lane)
    uint32_t aAddr = sb + (uint32_t)(mBase + (lane & 15)) * RSTRIDE
                   + (uint32_t)((lane >> 4) << 3) * 2;
    uint32_t bAddr = sb + sB
                   + (uint32_t)(nBase + (((lane >> 4) & 1) << 3) + (lane & 7)) * RSTRIDE
                   + (uint32_t)(((lane >> 3) & 1) << 3) * 2;

#pragma unroll
    for (int ks = 0; ks < 8; ++ks) {
        // B fragments: shared by both A passes (load once)
        uint32_t b[NF][2];
#pragma unroll
        for (int jj = 0; jj < NF / 2; ++jj) {
            uint32_t r[4];
            ldsm_x4(r, bAddr + jj * 16 * RSTRIDE + ks * 32);
            b[2 * jj][0] = r[0]; b[2 * jj][1] = r[1];
            b[2 * jj + 1][0] = r[2]; b[2 * jj + 1][1] = r[3];
        }
#pragma unroll
        for (int p = 0; p < 2; ++p) {        // A hi pass, A lo pass
            uint32_t aOff = p ? sAlo : 0u;
            uint32_t a[4][4];
#pragma unroll
            for (int i = 0; i < 4; ++i)
                ldsm_x4(a[i], aAddr + aOff + i * 16 * RSTRIDE + ks * 32);
#pragma unroll
            for (int i = 0; i < 4; ++i)
#pragma unroll
                for (int j = 0; j < NF; ++j)
                    mma16816(acc[i][j], a[i], b[j]);
        }
    }

    // ---- epilogue: add bias, store ----
    int outColBase = colBase - colBase0;
#pragma unroll
    for (int i = 0; i < 4; ++i) {
        int row0 = rowBase + mBase + i * 16 + (lane >> 2);
#pragma unroll
        for (int h = 0; h < 2; ++h) {
            int grow = row0 + h * 8;
            if (grow >= M) continue;
            float* crow = Cout + (size_t)grow * ldc + outColBase;
#pragma unroll
            for (int j = 0; j < NF; ++j) {
                int c = nBase + j * 8 + ((lane & 3) << 1);
                float2 v;
                v.x = acc[i][j][h * 2 + 0] + bias[colBase + c];
                v.y = acc[i][j][h * 2 + 1] + bias[colBase + c + 1];
                *(float2*)(crow + c) = v;
            }
        }
    }
}

// ---------------- skip/FiLM init: O = relu(gamma_s * lin + beta_s) ---------
__global__ void skip_init_kernel()
{
    int i = blockIdx.x * blockDim.x + threadIdx.x;
    int total = N_NODES * 32;
    if (i >= total) return;
    int row = i >> 5;
    int q   = (i & 31) << 2;
    const float* base = &g_C[(size_t)row * NCOLS];
    float4 lin   = *reinterpret_cast<const float4*>(&base[q]);
    float4 beta  = *reinterpret_cast<const float4*>(&base[128 + q]);
    float4 gamma = *reinterpret_cast<const float4*>(&base[256 + q]);
    float4 o;
    o.x = fmaxf(gamma.x * lin.x + beta.x, 0.0f);
    o.y = fmaxf(gamma.y * lin.y + beta.y, 0.0f);
    o.z = fmaxf(gamma.z * lin.z + beta.z, 0.0f);
    o.w = fmaxf(gamma.w * lin.w + beta.w, 0.0f);
    *reinterpret_cast<float4*>(&g_O[(size_t)row * 128 + q]) = o;
}

// ---------------- edge message pass: one warp per edge ----------------------
__global__ void edge_kernel(const int* __restrict__ ei, const int* __restrict__ et)
{
    int gthread = blockIdx.x * blockDim.x + threadIdx.x;
    int warp = gthread >> 5;
    int lane = gthread & 31;
    if (warp >= NEDGE) return;

    int src = ei[warp];
    int dst = ei[NEDGE + warp];
    int r   = et[warp];

    const float* xl = &g_C[(size_t)src * NCOLS + 384 + r * 384];
    const float* bg = &g_C[(size_t)dst * NCOLS + 384 + r * 384 + 128];
    int c = g_cnt[dst * NREL + r];
    float inv = 1.0f / (float)(c > 0 ? c : 1);
    float* o = &g_O[(size_t)dst * 128];

    int j = lane << 2;
    float4 x4  = *reinterpret_cast<const float4*>(&xl[j]);
    float4 b4  = *reinterpret_cast<const float4*>(&bg[j]);
    float4 gmm = *reinterpret_cast<const float4*>(&bg[128 + j]);
    float v0 = fmaxf(gmm.x * x4.x + b4.x, 0.0f) * inv;
    float v1 = fmaxf(gmm.y * x4.y + b4.y, 0.0f) * inv;
    float v2 = fmaxf(gmm.z * x4.z + b4.z, 0.0f) * inv;
    float v3 = fmaxf(gmm.w * x4.w + b4.w, 0.0f) * inv;
    atomicAdd(&o[j + 0], v0);
    atomicAdd(&o[j + 1], v1);
    atomicAdd(&o[j + 2], v2);
    atomicAdd(&o[j + 3], v3);
}

// ---------------- launch ------------------------------------------------------
extern "C" void kernel_launch(void* const* d_in, const int* in_sizes, int n_in,
                              void* d_out, int out_size)
{
    const float* x           = (const float*)d_in[0];
    const int*   ei          = (const int*)d_in[1];
    const int*   et          = (const int*)d_in[2];
    const float* lin_skip_w  = (const float*)d_in[3];
    const float* film_skip_w = (const float*)d_in[4];
    const float* lins_w      = (const float*)d_in[5];
    const float* films_w     = (const float*)d_in[6];
    const float* films_b     = (const float*)d_in[7];
    const float* linear1_w   = (const float*)d_in[8];
    const float* linear1_b   = (const float*)d_in[9];
    float*       out         = (float*)d_out;

    void *pC, *pO, *pWh, *pBias;
    cudaGetSymbolAddress(&pC,   g_C);
    cudaGetSymbolAddress(&pO,   g_O);
    cudaGetSymbolAddress(&pWh,  g_Wh);
    cudaGetSymbolAddress(&pBias, g_biasv);

    const int SMEM_MAIN = 2 * 128 * RSTRIDE + 256 * RSTRIDE;  // 139264
    const int SMEM_FIN  = 2 * 128 * RSTRIDE + 128 * RSTRIDE;  // 104448
    cudaFuncSetAttribute((const void*)mma_gemm_kernel<256, false>,
                         cudaFuncAttributeMaxDynamicSharedMemorySize, SMEM_MAIN);
    cudaFuncSetAttribute((const void*)mma_gemm_kernel<128, true>,
                         cudaFuncAttributeMaxDynamicSharedMemorySize, SMEM_FIN);

    // 1. prep: pack W^T fp16 + bias (incl. linear1)
    pack_wt_kernel<<<(NCOLSW * DIM + 255) / 256, 256>>>(
        lin_skip_w, film_skip_w, lins_w, films_w, films_b, linear1_w, linear1_b);

    // 2. zero counts, count edges per (dst, relation)
    zero_cnt_kernel<<<(N_NODES * NREL + 255) / 256, 256>>>();
    cnt_kernel<<<(NEDGE + 255) / 256, 256>>>(ei, et);

    // 3. fused node GEMM (HMMA fp16, A-split): C[N, 2304] = x @ Wpack + bias
    {
        dim3 grid((N_NODES + 127) / 128, NCOLS / 256);
        mma_gemm_kernel<256, false><<<grid, 256, SMEM_MAIN>>>(
            x, (const __half*)pWh, (const float*)pBias,
            (float*)pC, NCOLS, 0, N_NODES);
    }

    // 4. skip/FiLM init of O
    skip_init_kernel<<<(N_NODES * 32 + 255) / 256, 256>>>();

    // 5. edge message pass (one warp per edge)
    {
        int threads = 256;
        int wpb = threads / 32;
        int blocks = (NEDGE + wpb - 1) / wpb;
        edge_kernel<<<blocks, threads>>>(ei, et);
    }

    // 6+7. final projection with fused exact GELU:
    //      out = gelu(O) @ linear1_w + linear1_b
    {
        dim3 grid((N_NODES + 127) / 128, 1);
        mma_gemm_kernel<128, true><<<grid, 256, SMEM_FIN>>>(
            (const float*)pO, (const __half*)pWh, (const float*)pBias,
            out, 128, NCOLS, N_NODES);
    }
}

// round 7
// speedup vs baseline: 1.8139x; 1.1497x over previous
#include <cuda_runtime.h>
#include <cuda_fp16.h>
#include <math.h>
#include <stdint.h>

// Problem constants (fixed shapes)
#define N_NODES 100000
#define DIM     128
#define NEDGE   600000
#define NREL    5
#define NCOLS   2304          // 128 lin_skip + 256 film_skip + 5*(128 lins + 256 films)
#define NCOLSW  2432          // + 128 cols for linear1_w (final projection)

// ---------------- scratch (device globals; no allocation allowed) ----------
__device__ float  g_C[(size_t)N_NODES * NCOLS]; // fused node-GEMM output
__device__ float  g_O[(size_t)N_NODES * DIM];   // aggregated "out" (pre-GELU)
__device__ __half g_Wh[(size_t)NCOLSW * DIM];   // W^T fp16: [c][k]
__device__ float  g_biasv[NCOLSW];              // packed bias
__device__ int    g_cnt[N_NODES * NREL];        // per (dst, rel) edge count

// ---------------- PTX helpers (base PTX only; no 'a' features) -------------
__device__ __forceinline__ uint32_t smem_u32(const void* p) {
    uint32_t a;
    asm("{ .reg .u64 t; cvta.to.shared.u64 t, %1; cvt.u32.u64 %0, t; }"
        : "=r"(a) : "l"(p));
    return a;
}

__device__ __forceinline__ void ldsm_x4(uint32_t (&r)[4], uint32_t addr) {
    asm volatile("ldmatrix.sync.aligned.m8n8.x4.shared.b16 {%0,%1,%2,%3}, [%4];"
                 : "=r"(r[0]), "=r"(r[1]), "=r"(r[2]), "=r"(r[3]) : "r"(addr));
}
__device__ __forceinline__ void mma16816(float (&d)[4], const uint32_t (&a)[4],
                                         const uint32_t (&b)[2]) {
    asm volatile(
        "mma.sync.aligned.m16n8k16.row.col.f32.f16.f16.f32 "
        "{%0,%1,%2,%3}, {%4,%5,%6,%7}, {%8,%9}, {%0,%1,%2,%3};"
        : "+f"(d[0]), "+f"(d[1]), "+f"(d[2]), "+f"(d[3])
        : "r"(a[0]), "r"(a[1]), "r"(a[2]), "r"(a[3]), "r"(b[0]), "r"(b[1]));
}

__device__ __forceinline__ uint32_t pack2h(__half a, __half b) {
    __half2 t = __halves2half2(a, b);
    return *reinterpret_cast<uint32_t*>(&t);
}

// ---------------- prep kernels ----------------------------------------------
__global__ void pack_wt_kernel(const float* __restrict__ lin_skip_w,
                               const float* __restrict__ film_skip_w,
                               const float* __restrict__ lins_w,
                               const float* __restrict__ films_w,
                               const float* __restrict__ films_b,
                               const float* __restrict__ linear1_w,
                               const float* __restrict__ linear1_b)
{
    int idx = blockIdx.x * blockDim.x + threadIdx.x;   // over NCOLSW*128
    if (idx < NCOLSW * DIM) {
        int c = idx / DIM;
        int k = idx % DIM;
        float v;
        if (c < 128) {
            v = lin_skip_w[k * 128 + c];
        } else if (c < 384) {
            v = film_skip_w[k * 256 + (c - 128)];
        } else if (c < NCOLS) {
            int r  = (c - 384) / 384;
            int cc = (c - 384) % 384;
            if (cc < 128) v = lins_w[((size_t)r * 128 + k) * 128 + cc];
            else          v = films_w[((size_t)r * 128 + k) * 256 + (cc - 128)];
        } else {
            v = linear1_w[k * 128 + (c - NCOLS)];
        }
        g_Wh[idx] = __float2half_rn(v);
    }
    if (idx < NCOLSW) {
        float b = 0.0f;
        if (idx >= 384 && idx < NCOLS) {
            int r  = (idx - 384) / 384;
            int cc = (idx - 384) % 384;
            if (cc >= 128) b = films_b[r * 256 + (cc - 128)];
        } else if (idx >= NCOLS) {
            b = linear1_b[idx - NCOLS];
        }
        g_biasv[idx] = b;
    }
}

__global__ void zero_cnt_kernel()
{
    int i = blockIdx.x * blockDim.x + threadIdx.x;
    if (i < N_NODES * NREL) g_cnt[i] = 0;
}

__global__ void cnt_kernel(const int* __restrict__ ei, const int* __restrict__ et)
{
    int e = blockIdx.x * blockDim.x + threadIdx.x;
    if (e < NEDGE) {
        int dst = ei[NEDGE + e];
        int r   = et[e];
        atomicAdd(&g_cnt[dst * NREL + r], 1);
    }
}

// ---------------- mma.sync GEMM (fp16 A-split hi/lo, 2 passes) --------------
// C[128 x TN] tile per CTA; whole K=128 resident in SMEM.
// TN=128 -> SMEM 104448 B -> 2 CTAs/SM (16 warps) for latency hiding.
#define RSTRIDE 272

template <int TN, bool GELU>
__global__ void __launch_bounds__(256, 2)
mma_gemm_kernel(const float* __restrict__ A,
                const __half* __restrict__ W,
                const float* __restrict__ bias,
                float* __restrict__ Cout, int ldc,
                int colBase0, int M)
{
    constexpr int NF = TN / 32;   // n-fragments per warp (warp tile = 64 x TN/4)
    extern __shared__ char smem[];
    uint32_t sb = smem_u32(smem);

    int tid  = threadIdx.x;
    int wid  = tid >> 5;
    int lane = tid & 31;
    int rowBase = blockIdx.x * 128;
    int colBase = colBase0 + blockIdx.y * TN;

    const uint32_t sAlo = 128 * RSTRIDE;          // 34816
    const uint32_t sB   = 2 * 128 * RSTRIDE;      // 69632

    // ---- stage A: read fp32, (optional gelu), split to fp16 hi/lo ----
    for (int i = tid; i < 128 * 16; i += 256) {
        int row = i >> 4, ch = i & 15;            // ch indexes 8-float chunks
        int grow = rowBase + row;
        float v[8];
        if (grow < M) {
            float4 f0 = *(const float4*)(A + (size_t)grow * DIM + ch * 8);
            float4 f1 = *(const float4*)(A + (size_t)grow * DIM + ch * 8 + 4);
            v[0]=f0.x; v[1]=f0.y; v[2]=f0.z; v[3]=f0.w;
            v[4]=f1.x; v[5]=f1.y; v[6]=f1.z; v[7]=f1.w;
        } else {
#pragma unroll
            for (int j = 0; j < 8; ++j) v[j] = 0.0f;
        }
        if (GELU) {
#pragma unroll
            for (int j = 0; j < 8; ++j)
                v[j] = 0.5f * v[j] * (1.0f + erff(v[j] * 0.70710678118654752f));
        }
        __half h[8], l[8];
#pragma unroll
        for (int j = 0; j < 8; ++j) {
            h[j] = __float2half_rn(v[j]);
            l[j] = __float2half_rn(v[j] - __half2float(h[j]));
        }
        uint4 uh, ul;
        uh.x = pack2h(h[0], h[1]); uh.y = pack2h(h[2], h[3]);
        uh.z = pack2h(h[4], h[5]); uh.w = pack2h(h[6], h[7]);
        ul.x = pack2h(l[0], l[1]); ul.y = pack2h(l[2], l[3]);
        ul.z = pack2h(l[4], l[5]); ul.w = pack2h(l[6], l[7]);
        *(uint4*)(smem + row * RSTRIDE + ch * 16)        = uh;
        *(uint4*)(smem + sAlo + row * RSTRIDE + ch * 16) = ul;
    }
    // ---- stage B (fp16 W^T rows) ----
    for (int i = tid; i < TN * 16; i += 256) {
        int row = i >> 4, ch = i & 15;
        int gc = colBase + row;
        *(uint4*)(smem + sB + row * RSTRIDE + ch * 16) =
            *(const uint4*)(W + (size_t)gc * DIM + ch * 8);
    }
    __syncthreads();

    int mBase = (wid >> 2) * 64;
    int nBase = (wid & 3) * (TN / 4);

    float acc[4][NF][4];
#pragma unroll
    for (int i = 0; i < 4; ++i)
#pragma unroll
        for (int j = 0; j < NF; ++j)
#pragma unroll
            for (int q = 0; q < 4; ++q) acc[i][j][q] = 0.0f;

    // ldmatrix base addresses (per-lane)
    uint32_t aAddr = sb + (uint32_t)(mBase + (lane & 15)) * RSTRIDE
                   + (uint32_t)((lane >> 4) << 3) * 2;
    uint32_t bAddr = sb + sB
                   + (uint32_t)(nBase + (((lane >> 4) & 1) << 3) + (lane & 7)) * RSTRIDE
                   + (uint32_t)(((lane >> 3) & 1) << 3) * 2;

#pragma unroll
    for (int ks = 0; ks < 8; ++ks) {
        // B fragments: shared by both A passes (load once)
        uint32_t b[NF][2];
#pragma unroll
        for (int jj = 0; jj < NF / 2; ++jj) {
            uint32_t r[4];
            ldsm_x4(r, bAddr + jj * 16 * RSTRIDE + ks * 32);
            b[2 * jj][0] = r[0]; b[2 * jj][1] = r[1];
            b[2 * jj + 1][0] = r[2]; b[2 * jj + 1][1] = r[3];
        }
#pragma unroll
        for (int p = 0; p < 2; ++p) {        // A hi pass, A lo pass
            uint32_t aOff = p ? sAlo : 0u;
            uint32_t a[4][4];
#pragma unroll
            for (int i = 0; i < 4; ++i)
                ldsm_x4(a[i], aAddr + aOff + i * 16 * RSTRIDE + ks * 32);
#pragma unroll
            for (int i = 0; i < 4; ++i)
#pragma unroll
                for (int j = 0; j < NF; ++j)
                    mma16816(acc[i][j], a[i], b[j]);
        }
    }

    // ---- epilogue: add bias, store ----
    int outColBase = colBase - colBase0;
#pragma unroll
    for (int i = 0; i < 4; ++i) {
        int row0 = rowBase + mBase + i * 16 + (lane >> 2);
#pragma unroll
        for (int h = 0; h < 2; ++h) {
            int grow = row0 + h * 8;
            if (grow >= M) continue;
            float* crow = Cout + (size_t)grow * ldc + outColBase;
#pragma unroll
            for (int j = 0; j < NF; ++j) {
                int c = nBase + j * 8 + ((lane & 3) << 1);
                float2 v;
                v.x = acc[i][j][h * 2 + 0] + bias[colBase + c];
                v.y = acc[i][j][h * 2 + 1] + bias[colBase + c + 1];
                *(float2*)(crow + c) = v;
            }
        }
    }
}

// ---------------- skip/FiLM init: O = relu(gamma_s * lin + beta_s) ---------
__global__ void skip_init_kernel()
{
    int i = blockIdx.x * blockDim.x + threadIdx.x;
    int total = N_NODES * 32;
    if (i >= total) return;
    int row = i >> 5;
    int q   = (i & 31) << 2;
    const float* base = &g_C[(size_t)row * NCOLS];
    float4 lin   = *reinterpret_cast<const float4*>(&base[q]);
    float4 beta  = *reinterpret_cast<const float4*>(&base[128 + q]);
    float4 gamma = *reinterpret_cast<const float4*>(&base[256 + q]);
    float4 o;
    o.x = fmaxf(gamma.x * lin.x + beta.x, 0.0f);
    o.y = fmaxf(gamma.y * lin.y + beta.y, 0.0f);
    o.z = fmaxf(gamma.z * lin.z + beta.z, 0.0f);
    o.w = fmaxf(gamma.w * lin.w + beta.w, 0.0f);
    *reinterpret_cast<float4*>(&g_O[(size_t)row * 128 + q]) = o;
}

// ---------------- edge message pass: one warp per edge ----------------------
__global__ void edge_kernel(const int* __restrict__ ei, const int* __restrict__ et)
{
    int gthread = blockIdx.x * blockDim.x + threadIdx.x;
    int warp = gthread >> 5;
    int lane = gthread & 31;
    if (warp >= NEDGE) return;

    int src = ei[warp];
    int dst = ei[NEDGE + warp];
    int r   = et[warp];

    const float* xl = &g_C[(size_t)src * NCOLS + 384 + r * 384];
    const float* bg = &g_C[(size_t)dst * NCOLS + 384 + r * 384 + 128];
    int c = g_cnt[dst * NREL + r];
    float inv = 1.0f / (float)(c > 0 ? c : 1);
    float* o = &g_O[(size_t)dst * 128];

    int j = lane << 2;
    float4 x4  = *reinterpret_cast<const float4*>(&xl[j]);
    float4 b4  = *reinterpret_cast<const float4*>(&bg[j]);
    float4 gmm = *reinterpret_cast<const float4*>(&bg[128 + j]);
    float v0 = fmaxf(gmm.x * x4.x + b4.x, 0.0f) * inv;
    float v1 = fmaxf(gmm.y * x4.y + b4.y, 0.0f) * inv;
    float v2 = fmaxf(gmm.z * x4.z + b4.z, 0.0f) * inv;
    float v3 = fmaxf(gmm.w * x4.w + b4.w, 0.0f) * inv;
    atomicAdd(&o[j + 0], v0);
    atomicAdd(&o[j + 1], v1);
    atomicAdd(&o[j + 2], v2);
    atomicAdd(&o[j + 3], v3);
}

// ---------------- launch ------------------------------------------------------
extern "C" void kernel_launch(void* const* d_in, const int* in_sizes, int n_in,
                              void* d_out, int out_size)
{
    const float* x           = (const float*)d_in[0];
    const int*   ei          = (const int*)d_in[1];
    const int*   et          = (const int*)d_in[2];
    const float* lin_skip_w  = (const float*)d_in[3];
    const float* film_skip_w = (const float*)d_in[4];
    const float* lins_w      = (const float*)d_in[5];
    const float* films_w     = (const float*)d_in[6];
    const float* films_b     = (const float*)d_in[7];
    const float* linear1_w   = (const float*)d_in[8];
    const float* linear1_b   = (const float*)d_in[9];
    float*       out         = (float*)d_out;

    void *pC, *pO, *pWh, *pBias;
    cudaGetSymbolAddress(&pC,   g_C);
    cudaGetSymbolAddress(&pO,   g_O);
    cudaGetSymbolAddress(&pWh,  g_Wh);
    cudaGetSymbolAddress(&pBias, g_biasv);

    const int SMEM_T128 = 2 * 128 * RSTRIDE + 128 * RSTRIDE;  // 104448
    cudaFuncSetAttribute((const void*)mma_gemm_kernel<128, false>,
                         cudaFuncAttributeMaxDynamicSharedMemorySize, SMEM_T128);
    cudaFuncSetAttribute((const void*)mma_gemm_kernel<128, true>,
                         cudaFuncAttributeMaxDynamicSharedMemorySize, SMEM_T128);

    // 1. prep: pack W^T fp16 + bias (incl. linear1)
    pack_wt_kernel<<<(NCOLSW * DIM + 255) / 256, 256>>>(
        lin_skip_w, film_skip_w, lins_w, films_w, films_b, linear1_w, linear1_b);

    // 2. zero counts, count edges per (dst, relation)
    zero_cnt_kernel<<<(N_NODES * NREL + 255) / 256, 256>>>();
    cnt_kernel<<<(NEDGE + 255) / 256, 256>>>(ei, et);

    // 3. fused node GEMM (HMMA fp16, A-split): C[N, 2304] = x @ Wpack + bias
    {
        dim3 grid((N_NODES + 127) / 128, NCOLS / 128);
        mma_gemm_kernel<128, false><<<grid, 256, SMEM_T128>>>(
            x, (const __half*)pWh, (const float*)pBias,
            (float*)pC, NCOLS, 0, N_NODES);
    }

    // 4. skip/FiLM init of O
    skip_init_kernel<<<(N_NODES * 32 + 255) / 256, 256>>>();

    // 5. edge message pass (one warp per edge)
    {
        int threads = 256;
        int wpb = threads / 32;
        int blocks = (NEDGE + wpb - 1) / wpb;
        edge_kernel<<<blocks, threads>>>(ei, et);
    }

    // 6+7. final projection with fused exact GELU:
    //      out = gelu(O) @ linear1_w + linear1_b
    {
        dim3 grid((N_NODES + 127) / 128, 1);
        mma_gemm_kernel<128, true><<<grid, 256, SMEM_T128>>>(
            (const float*)pO, (const __half*)pWh, (const float*)pBias,
            out, 128, NCOLS, N_NODES);
    }
}

// round 8
// speedup vs baseline: 2.0651x; 1.1385x over previous
#include <cuda_runtime.h>
#include <cuda_fp16.h>
#include <math.h>
#include <stdint.h>

// Problem constants (fixed shapes)
#define N_NODES 100000
#define DIM     128
#define NEDGE   600000
#define NREL    5
#define NCOLS   2304          // 128 lin_skip + 256 film_skip + 5*(128 lins + 256 films)
#define NCOLSW  2432          // + 128 cols for linear1_w (final projection)

// ---------------- scratch (device globals; no allocation allowed) ----------
__device__ float  g_C[(size_t)N_NODES * NCOLS]; // fused node-GEMM output
__device__ float  g_O[(size_t)N_NODES * DIM];   // aggregated "out" (pre-GELU)
__device__ __half g_xh[(size_t)N_NODES * DIM];  // x in fp16
__device__ __half g_Wh[(size_t)NCOLSW * DIM];   // W^T fp16: [c][k]
__device__ float  g_biasv[NCOLSW];              // packed bias
__device__ int    g_cnt[N_NODES * NREL];        // per (dst, rel) edge count

// ---------------- PTX helpers (base PTX only; no 'a' features) -------------
__device__ __forceinline__ uint32_t smem_u32(const void* p) {
    uint32_t a;
    asm("{ .reg .u64 t; cvta.to.shared.u64 t, %1; cvt.u32.u64 %0, t; }"
        : "=r"(a) : "l"(p));
    return a;
}

__device__ __forceinline__ void ldsm_x4(uint32_t (&r)[4], uint32_t addr) {
    asm volatile("ldmatrix.sync.aligned.m8n8.x4.shared.b16 {%0,%1,%2,%3}, [%4];"
                 : "=r"(r[0]), "=r"(r[1]), "=r"(r[2]), "=r"(r[3]) : "r"(addr));
}
__device__ __forceinline__ void mma16816(float (&d)[4], const uint32_t (&a)[4],
                                         const uint32_t (&b)[2]) {
    asm volatile(
        "mma.sync.aligned.m16n8k16.row.col.f32.f16.f16.f32 "
        "{%0,%1,%2,%3}, {%4,%5,%6,%7}, {%8,%9}, {%0,%1,%2,%3};"
        : "+f"(d[0]), "+f"(d[1]), "+f"(d[2]), "+f"(d[3])
        : "r"(a[0]), "r"(a[1]), "r"(a[2]), "r"(a[3]), "r"(b[0]), "r"(b[1]));
}

__device__ __forceinline__ uint32_t pack2h(__half a, __half b) {
    __half2 t = __halves2half2(a, b);
    return *reinterpret_cast<uint32_t*>(&t);
}

// ---------------- prep kernels ----------------------------------------------
__global__ void split_x_kernel(const float* __restrict__ x)
{
    int i = blockIdx.x * blockDim.x + threadIdx.x;
    if (i >= N_NODES * DIM) return;
    g_xh[i] = __float2half_rn(x[i]);
}

__global__ void pack_wt_kernel(const float* __restrict__ lin_skip_w,
                               const float* __restrict__ film_skip_w,
                               const float* __restrict__ lins_w,
                               const float* __restrict__ films_w,
                               const float* __restrict__ films_b,
                               const float* __restrict__ linear1_w,
                               const float* __restrict__ linear1_b)
{
    int idx = blockIdx.x * blockDim.x + threadIdx.x;   // over NCOLSW*128
    if (idx < NCOLSW * DIM) {
        int c = idx / DIM;
        int k = idx % DIM;
        float v;
        if (c < 128) {
            v = lin_skip_w[k * 128 + c];
        } else if (c < 384) {
            v = film_skip_w[k * 256 + (c - 128)];
        } else if (c < NCOLS) {
            int r  = (c - 384) / 384;
            int cc = (c - 384) % 384;
            if (cc < 128) v = lins_w[((size_t)r * 128 + k) * 128 + cc];
            else          v = films_w[((size_t)r * 128 + k) * 256 + (cc - 128)];
        } else {
            v = linear1_w[k * 128 + (c - NCOLS)];
        }
        g_Wh[idx] = __float2half_rn(v);
    }
    if (idx < NCOLSW) {
        float b = 0.0f;
        if (idx >= 384 && idx < NCOLS) {
            int r  = (idx - 384) / 384;
            int cc = (idx - 384) % 384;
            if (cc >= 128) b = films_b[r * 256 + (cc - 128)];
        } else if (idx >= NCOLS) {
            b = linear1_b[idx - NCOLS];
        }
        g_biasv[idx] = b;
    }
}

__global__ void zero_cnt_kernel()
{
    int i = blockIdx.x * blockDim.x + threadIdx.x;
    if (i < N_NODES * NREL) g_cnt[i] = 0;
}

__global__ void cnt_kernel(const int* __restrict__ ei, const int* __restrict__ et)
{
    int e = blockIdx.x * blockDim.x + threadIdx.x;
    if (e < NEDGE) {
        int dst = ei[NEDGE + e];
        int r   = et[e];
        atomicAdd(&g_cnt[dst * NREL + r], 1);
    }
}

// ---------------- mma.sync GEMM (pure fp16, single pass) --------------------
// C[128 x TN] tile per CTA; whole K=128 resident in SMEM.
// GELU=false: A staged by 16B copies from fp16 g_xh.
// GELU=true : A staged from fp32 src with exact-erf GELU + fp16 convert.
// SMEM = A 34816 + B 34816 = 69632 B.
#define RSTRIDE 272

template <int TN, bool GELU>
__global__ void __launch_bounds__(256, 2)
mma_gemm_kernel(const __half* __restrict__ Ah,
                const float* __restrict__ Af,
                const __half* __restrict__ W,
                const float* __restrict__ bias,
                float* __restrict__ Cout, int ldc,
                int colBase0, int M)
{
    constexpr int NF = TN / 32;   // n-fragments per warp (warp tile = 64 x TN/4)
    extern __shared__ char smem[];
    uint32_t sb = smem_u32(smem);

    int tid  = threadIdx.x;
    int wid  = tid >> 5;
    int lane = tid & 31;
    int rowBase = blockIdx.x * 128;
    int colBase = colBase0 + blockIdx.y * TN;

    const uint32_t sB = 128 * RSTRIDE;   // 34816

    // ---- stage A ----
    if (!GELU) {
        // pure fp16 copy: 128 rows x 16 chunks of 16B
        for (int i = tid; i < 128 * 16; i += 256) {
            int row = i >> 4, ch = i & 15;
            int grow = rowBase + row;
            uint4 v = make_uint4(0, 0, 0, 0);
            if (grow < M)
                v = *(const uint4*)(Ah + (size_t)grow * DIM + ch * 8);
            *(uint4*)(smem + row * RSTRIDE + ch * 16) = v;
        }
    } else {
        // fp32 read -> gelu -> fp16
        for (int i = tid; i < 128 * 16; i += 256) {
            int row = i >> 4, ch = i & 15;
            int grow = rowBase + row;
            float v[8];
            if (grow < M) {
                float4 f0 = *(const float4*)(Af + (size_t)grow * DIM + ch * 8);
                float4 f1 = *(const float4*)(Af + (size_t)grow * DIM + ch * 8 + 4);
                v[0]=f0.x; v[1]=f0.y; v[2]=f0.z; v[3]=f0.w;
                v[4]=f1.x; v[5]=f1.y; v[6]=f1.z; v[7]=f1.w;
            } else {
#pragma unroll
                for (int j = 0; j < 8; ++j) v[j] = 0.0f;
            }
#pragma unroll
            for (int j = 0; j < 8; ++j)
                v[j] = 0.5f * v[j] * (1.0f + erff(v[j] * 0.70710678118654752f));
            uint4 uh;
            uh.x = pack2h(__float2half_rn(v[0]), __float2half_rn(v[1]));
            uh.y = pack2h(__float2half_rn(v[2]), __float2half_rn(v[3]));
            uh.z = pack2h(__float2half_rn(v[4]), __float2half_rn(v[5]));
            uh.w = pack2h(__float2half_rn(v[6]), __float2half_rn(v[7]));
            *(uint4*)(smem + row * RSTRIDE + ch * 16) = uh;
        }
    }
    // ---- stage B (fp16 W^T rows) ----
    for (int i = tid; i < TN * 16; i += 256) {
        int row = i >> 4, ch = i & 15;
        int gc = colBase + row;
        *(uint4*)(smem + sB + row * RSTRIDE + ch * 16) =
            *(const uint4*)(W + (size_t)gc * DIM + ch * 8);
    }
    __syncthreads();

    int mBase = (wid >> 2) * 64;
    int nBase = (wid & 3) * (TN / 4);

    float acc[4][NF][4];
#pragma unroll
    for (int i = 0; i < 4; ++i)
#pragma unroll
        for (int j = 0; j < NF; ++j)
#pragma unroll
            for (int q = 0; q < 4; ++q) acc[i][j][q] = 0.0f;

    // ldmatrix base addresses (per-lane)
    uint32_t aAddr = sb + (uint32_t)(mBase + (lane & 15)) * RSTRIDE
                   + (uint32_t)((lane >> 4) << 3) * 2;
    uint32_t bAddr = sb + sB
                   + (uint32_t)(nBase + (((lane >> 4) & 1) << 3) + (lane & 7)) * RSTRIDE
                   + (uint32_t)(((lane >> 3) & 1) << 3) * 2;

#pragma unroll
    for (int ks = 0; ks < 8; ++ks) {
        uint32_t b[NF][2];
#pragma unroll
        for (int jj = 0; jj < NF / 2; ++jj) {
            uint32_t r[4];
            ldsm_x4(r, bAddr + jj * 16 * RSTRIDE + ks * 32);
            b[2 * jj][0] = r[0]; b[2 * jj][1] = r[1];
            b[2 * jj + 1][0] = r[2]; b[2 * jj + 1][1] = r[3];
        }
        uint32_t a[4][4];
#pragma unroll
        for (int i = 0; i < 4; ++i)
            ldsm_x4(a[i], aAddr + i * 16 * RSTRIDE + ks * 32);
#pragma unroll
        for (int i = 0; i < 4; ++i)
#pragma unroll
            for (int j = 0; j < NF; ++j)
                mma16816(acc[i][j], a[i], b[j]);
    }

    // ---- epilogue: add bias, store ----
    int outColBase = colBase - colBase0;
#pragma unroll
    for (int i = 0; i < 4; ++i) {
        int row0 = rowBase + mBase + i * 16 + (lane >> 2);
#pragma unroll
        for (int h = 0; h < 2; ++h) {
            int grow = row0 + h * 8;
            if (grow >= M) continue;
            float* crow = Cout + (size_t)grow * ldc + outColBase;
#pragma unroll
            for (int j = 0; j < NF; ++j) {
                int c = nBase + j * 8 + ((lane & 3) << 1);
                float2 v;
                v.x = acc[i][j][h * 2 + 0] + bias[colBase + c];
                v.y = acc[i][j][h * 2 + 1] + bias[colBase + c + 1];
                *(float2*)(crow + c) = v;
            }
        }
    }
}

// ---------------- skip/FiLM init: O = relu(gamma_s * lin + beta_s) ---------
__global__ void skip_init_kernel()
{
    int i = blockIdx.x * blockDim.x + threadIdx.x;
    int total = N_NODES * 32;
    if (i >= total) return;
    int row = i >> 5;
    int q   = (i & 31) << 2;
    const float* base = &g_C[(size_t)row * NCOLS];
    float4 lin   = *reinterpret_cast<const float4*>(&base[q]);
    float4 beta  = *reinterpret_cast<const float4*>(&base[128 + q]);
    float4 gamma = *reinterpret_cast<const float4*>(&base[256 + q]);
    float4 o;
    o.x = fmaxf(gamma.x * lin.x + beta.x, 0.0f);
    o.y = fmaxf(gamma.y * lin.y + beta.y, 0.0f);
    o.z = fmaxf(gamma.z * lin.z + beta.z, 0.0f);
    o.w = fmaxf(gamma.w * lin.w + beta.w, 0.0f);
    *reinterpret_cast<float4*>(&g_O[(size_t)row * 128 + q]) = o;
}

// ---------------- edge message pass: one warp per edge ----------------------
__global__ void edge_kernel(const int* __restrict__ ei, const int* __restrict__ et)
{
    int gthread = blockIdx.x * blockDim.x + threadIdx.x;
    int warp = gthread >> 5;
    int lane = gthread & 31;
    if (warp >= NEDGE) return;

    int src = ei[warp];
    int dst = ei[NEDGE + warp];
    int r   = et[warp];

    const float* xl = &g_C[(size_t)src * NCOLS + 384 + r * 384];
    const float* bg = &g_C[(size_t)dst * NCOLS + 384 + r * 384 + 128];
    int c = g_cnt[dst * NREL + r];
    float inv = 1.0f / (float)(c > 0 ? c : 1);
    float* o = &g_O[(size_t)dst * 128];

    int j = lane << 2;
    float4 x4  = *reinterpret_cast<const float4*>(&xl[j]);
    float4 b4  = *reinterpret_cast<const float4*>(&bg[j]);
    float4 gmm = *reinterpret_cast<const float4*>(&bg[128 + j]);
    float v0 = fmaxf(gmm.x * x4.x + b4.x, 0.0f) * inv;
    float v1 = fmaxf(gmm.y * x4.y + b4.y, 0.0f) * inv;
    float v2 = fmaxf(gmm.z * x4.z + b4.z, 0.0f) * inv;
    float v3 = fmaxf(gmm.w * x4.w + b4.w, 0.0f) * inv;
    atomicAdd(&o[j + 0], v0);
    atomicAdd(&o[j + 1], v1);
    atomicAdd(&o[j + 2], v2);
    atomicAdd(&o[j + 3], v3);
}

// ---------------- launch ------------------------------------------------------
extern "C" void kernel_launch(void* const* d_in, const int* in_sizes, int n_in,
                              void* d_out, int out_size)
{
    const float* x           = (const float*)d_in[0];
    const int*   ei          = (const int*)d_in[1];
    const int*   et          = (const int*)d_in[2];
    const float* lin_skip_w  = (const float*)d_in[3];
    const float* film_skip_w = (const float*)d_in[4];
    const float* lins_w      = (const float*)d_in[5];
    const float* films_w     = (const float*)d_in[6];
    const float* films_b     = (const float*)d_in[7];
    const float* linear1_w   = (const float*)d_in[8];
    const float* linear1_b   = (const float*)d_in[9];
    float*       out         = (float*)d_out;

    void *pC, *pO, *pXh, *pWh, *pBias;
    cudaGetSymbolAddress(&pC,   g_C);
    cudaGetSymbolAddress(&pO,   g_O);
    cudaGetSymbolAddress(&pXh,  g_xh);
    cudaGetSymbolAddress(&pWh,  g_Wh);
    cudaGetSymbolAddress(&pBias, g_biasv);

    const int SMEM_T128 = 128 * RSTRIDE + 128 * RSTRIDE;  // 69632
    cudaFuncSetAttribute((const void*)mma_gemm_kernel<128, false>,
                         cudaFuncAttributeMaxDynamicSharedMemorySize, SMEM_T128);
    cudaFuncSetAttribute((const void*)mma_gemm_kernel<128, true>,
                         cudaFuncAttributeMaxDynamicSharedMemorySize, SMEM_T128);

    // 1. prep: x -> fp16; pack W^T fp16 + bias (incl. linear1)
    split_x_kernel<<<(N_NODES * DIM + 255) / 256, 256>>>(x);
    pack_wt_kernel<<<(NCOLSW * DIM + 255) / 256, 256>>>(
        lin_skip_w, film_skip_w, lins_w, films_w, films_b, linear1_w, linear1_b);

    // 2. zero counts, count edges per (dst, relation)
    zero_cnt_kernel<<<(N_NODES * NREL + 255) / 256, 256>>>();
    cnt_kernel<<<(NEDGE + 255) / 256, 256>>>(ei, et);

    // 3. fused node GEMM (HMMA fp16 single pass): C[N, 2304] = x @ Wpack + bias
    {
        dim3 grid((N_NODES + 127) / 128, NCOLS / 128);
        mma_gemm_kernel<128, false><<<grid, 256, SMEM_T128>>>(
            (const __half*)pXh, x, (const __half*)pWh, (const float*)pBias,
            (float*)pC, NCOLS, 0, N_NODES);
    }

    // 4. skip/FiLM init of O
    skip_init_kernel<<<(N_NODES * 32 + 255) / 256, 256>>>();

    // 5. edge message pass (one warp per edge)
    {
        int threads = 256;
        int wpb = threads / 32;
        int blocks = (NEDGE + wpb - 1) / wpb;
        edge_kernel<<<blocks, threads>>>(ei, et);
    }

    // 6+7. final projection with fused exact GELU:
    //      out = gelu(O) @ linear1_w + linear1_b
    {
        dim3 grid((N_NODES + 127) / 128, 1);
        mma_gemm_kernel<128, true><<<grid, 256, SMEM_T128>>>(
            (const __half*)pXh, (const float*)pO, (const __half*)pWh,
            (const float*)pBias, out, 128, NCOLS, N_NODES);
    }
}

// round 9
// speedup vs baseline: 2.6448x; 1.2807x over previous
#include <cuda_runtime.h>
#include <cuda_fp16.h>
#include <math.h>
#include <stdint.h>

// Problem constants (fixed shapes)
#define N_NODES 100000
#define DIM     128
#define NEDGE   600000
#define NREL    5
#define NCOLS   2304          // 128 lin_skip + 256 film_skip + 5*(128 lins + 256 films)
#define NCOLSW  2432          // + 128 cols for linear1_w (final projection)

// ---------------- scratch (device globals; no allocation allowed) ----------
__device__ __half g_C[(size_t)N_NODES * NCOLS]; // fused node-GEMM output (fp16)
__device__ float  g_O[(size_t)N_NODES * DIM];   // aggregated "out" (pre-GELU)
__device__ __half g_xh[(size_t)N_NODES * DIM];  // x in fp16
__device__ __half g_Wh[(size_t)NCOLSW * DIM];   // W^T fp16: [c][k]
__device__ float  g_biasv[NCOLSW];              // packed bias
__device__ int    g_cnt[N_NODES * NREL];        // per (dst, rel) edge count

// ---------------- PTX helpers (base PTX only; no 'a' features) -------------
__device__ __forceinline__ uint32_t smem_u32(const void* p) {
    uint32_t a;
    asm("{ .reg .u64 t; cvta.to.shared.u64 t, %1; cvt.u32.u64 %0, t; }"
        : "=r"(a) : "l"(p));
    return a;
}

__device__ __forceinline__ void ldsm_x4(uint32_t (&r)[4], uint32_t addr) {
    asm volatile("ldmatrix.sync.aligned.m8n8.x4.shared.b16 {%0,%1,%2,%3}, [%4];"
                 : "=r"(r[0]), "=r"(r[1]), "=r"(r[2]), "=r"(r[3]) : "r"(addr));
}
__device__ __forceinline__ void mma16816(float (&d)[4], const uint32_t (&a)[4],
                                         const uint32_t (&b)[2]) {
    asm volatile(
        "mma.sync.aligned.m16n8k16.row.col.f32.f16.f16.f32 "
        "{%0,%1,%2,%3}, {%4,%5,%6,%7}, {%8,%9}, {%0,%1,%2,%3};"
        : "+f"(d[0]), "+f"(d[1]), "+f"(d[2]), "+f"(d[3])
        : "r"(a[0]), "r"(a[1]), "r"(a[2]), "r"(a[3]), "r"(b[0]), "r"(b[1]));
}

__device__ __forceinline__ uint32_t pack2h(__half a, __half b) {
    __half2 t = __halves2half2(a, b);
    return *reinterpret_cast<uint32_t*>(&t);
}

// vector reduction (no return) — sm_90+ base PTX
__device__ __forceinline__ void red_add_v4(float* addr, float4 v) {
    asm volatile("red.global.add.v4.f32 [%0], {%1,%2,%3,%4};"
                 :: "l"(addr), "f"(v.x), "f"(v.y), "f"(v.z), "f"(v.w)
                 : "memory");
}

// ---------------- prep kernels ----------------------------------------------
__global__ void split_x_kernel(const float* __restrict__ x)
{
    int i = blockIdx.x * blockDim.x + threadIdx.x;
    if (i >= N_NODES * DIM) return;
    g_xh[i] = __float2half_rn(x[i]);
}

__global__ void pack_wt_kernel(const float* __restrict__ lin_skip_w,
                               const float* __restrict__ film_skip_w,
                               const float* __restrict__ lins_w,
                               const float* __restrict__ films_w,
                               const float* __restrict__ films_b,
                               const float* __restrict__ linear1_w,
                               const float* __restrict__ linear1_b)
{
    int idx = blockIdx.x * blockDim.x + threadIdx.x;   // over NCOLSW*128
    if (idx < NCOLSW * DIM) {
        int c = idx / DIM;
        int k = idx % DIM;
        float v;
        if (c < 128) {
            v = lin_skip_w[k * 128 + c];
        } else if (c < 384) {
            v = film_skip_w[k * 256 + (c - 128)];
        } else if (c < NCOLS) {
            int r  = (c - 384) / 384;
            int cc = (c - 384) % 384;
            if (cc < 128) v = lins_w[((size_t)r * 128 + k) * 128 + cc];
            else          v = films_w[((size_t)r * 128 + k) * 256 + (cc - 128)];
        } else {
            v = linear1_w[k * 128 + (c - NCOLS)];
        }
        g_Wh[idx] = __float2half_rn(v);
    }
    if (idx < NCOLSW) {
        float b = 0.0f;
        if (idx >= 384 && idx < NCOLS) {
            int r  = (idx - 384) / 384;
            int cc = (idx - 384) % 384;
            if (cc >= 128) b = films_b[r * 256 + (cc - 128)];
        } else if (idx >= NCOLS) {
            b = linear1_b[idx - NCOLS];
        }
        g_biasv[idx] = b;
    }
}

__global__ void zero_cnt_kernel()
{
    int i = blockIdx.x * blockDim.x + threadIdx.x;
    if (i < N_NODES * NREL) g_cnt[i] = 0;
}

__global__ void cnt_kernel(const int* __restrict__ ei, const int* __restrict__ et)
{
    int e = blockIdx.x * blockDim.x + threadIdx.x;
    if (e < NEDGE) {
        int dst = ei[NEDGE + e];
        int r   = et[e];
        atomicAdd(&g_cnt[dst * NREL + r], 1);
    }
}

// ---------------- mma.sync GEMM (pure fp16, single pass) --------------------
// C[128 x TN] tile per CTA; whole K=128 resident in SMEM.
// GELU=false: A staged by 16B copies from fp16 g_xh; output fp16.
// GELU=true : A staged from fp32 src with exact-erf GELU; output fp32.
// SMEM = A 34816 + B 34816 = 69632 B -> 2 CTAs/SM.
#define RSTRIDE 272

template <int TN, bool GELU, typename TOUT>
__global__ void __launch_bounds__(256, 2)
mma_gemm_kernel(const __half* __restrict__ Ah,
                const float* __restrict__ Af,
                const __half* __restrict__ W,
                const float* __restrict__ bias,
                TOUT* __restrict__ Cout, int ldc,
                int colBase0, int M)
{
    constexpr int NF = TN / 32;   // n-fragments per warp (warp tile = 64 x TN/4)
    extern __shared__ char smem[];
    uint32_t sb = smem_u32(smem);

    int tid  = threadIdx.x;
    int wid  = tid >> 5;
    int lane = tid & 31;
    int rowBase = blockIdx.x * 128;
    int colBase = colBase0 + blockIdx.y * TN;

    const uint32_t sB = 128 * RSTRIDE;   // 34816

    // ---- stage A ----
    if (!GELU) {
        for (int i = tid; i < 128 * 16; i += 256) {
            int row = i >> 4, ch = i & 15;
            int grow = rowBase + row;
            uint4 v = make_uint4(0, 0, 0, 0);
            if (grow < M)
                v = *(const uint4*)(Ah + (size_t)grow * DIM + ch * 8);
            *(uint4*)(smem + row * RSTRIDE + ch * 16) = v;
        }
    } else {
        for (int i = tid; i < 128 * 16; i += 256) {
            int row = i >> 4, ch = i & 15;
            int grow = rowBase + row;
            float v[8];
            if (grow < M) {
                float4 f0 = *(const float4*)(Af + (size_t)grow * DIM + ch * 8);
                float4 f1 = *(const float4*)(Af + (size_t)grow * DIM + ch * 8 + 4);
                v[0]=f0.x; v[1]=f0.y; v[2]=f0.z; v[3]=f0.w;
                v[4]=f1.x; v[5]=f1.y; v[6]=f1.z; v[7]=f1.w;
            } else {
#pragma unroll
                for (int j = 0; j < 8; ++j) v[j] = 0.0f;
            }
#pragma unroll
            for (int j = 0; j < 8; ++j)
                v[j] = 0.5f * v[j] * (1.0f + erff(v[j] * 0.70710678118654752f));
            uint4 uh;
            uh.x = pack2h(__float2half_rn(v[0]), __float2half_rn(v[1]));
            uh.y = pack2h(__float2half_rn(v[2]), __float2half_rn(v[3]));
            uh.z = pack2h(__float2half_rn(v[4]), __float2half_rn(v[5]));
            uh.w = pack2h(__float2half_rn(v[6]), __float2half_rn(v[7]));
            *(uint4*)(smem + row * RSTRIDE + ch * 16) = uh;
        }
    }
    // ---- stage B (fp16 W^T rows) ----
    for (int i = tid; i < TN * 16; i += 256) {
        int row = i >> 4, ch = i & 15;
        int gc = colBase + row;
        *(uint4*)(smem + sB + row * RSTRIDE + ch * 16) =
            *(const uint4*)(W + (size_t)gc * DIM + ch * 8);
    }
    __syncthreads();

    int mBase = (wid >> 2) * 64;
    int nBase = (wid & 3) * (TN / 4);

    float acc[4][NF][4];
#pragma unroll
    for (int i = 0; i < 4; ++i)
#pragma unroll
        for (int j = 0; j < NF; ++j)
#pragma unroll
            for (int q = 0; q < 4; ++q) acc[i][j][q] = 0.0f;

    // ldmatrix base addresses (per-lane)
    uint32_t aAddr = sb + (uint32_t)(mBase + (lane & 15)) * RSTRIDE
                   + (uint32_t)((lane >> 4) << 3) * 2;
    uint32_t bAddr = sb + sB
                   + (uint32_t)(nBase + (((lane >> 4) & 1) << 3) + (lane & 7)) * RSTRIDE
                   + (uint32_t)(((lane >> 3) & 1) << 3) * 2;

#pragma unroll
    for (int ks = 0; ks < 8; ++ks) {
        uint32_t b[NF][2];
#pragma unroll
        for (int jj = 0; jj < NF / 2; ++jj) {
            uint32_t r[4];
            ldsm_x4(r, bAddr + jj * 16 * RSTRIDE + ks * 32);
            b[2 * jj][0] = r[0]; b[2 * jj][1] = r[1];
            b[2 * jj + 1][0] = r[2]; b[2 * jj + 1][1] = r[3];
        }
        uint32_t a[4][4];
#pragma unroll
        for (int i = 0; i < 4; ++i)
            ldsm_x4(a[i], aAddr + i * 16 * RSTRIDE + ks * 32);
#pragma unroll
        for (int i = 0; i < 4; ++i)
#pragma unroll
            for (int j = 0; j < NF; ++j)
                mma16816(acc[i][j], a[i], b[j]);
    }

    // ---- epilogue: add bias (fp32), store (fp16 or fp32) ----
    int outColBase = colBase - colBase0;
#pragma unroll
    for (int i = 0; i < 4; ++i) {
        int row0 = rowBase + mBase + i * 16 + (lane >> 2);
#pragma unroll
        for (int h = 0; h < 2; ++h) {
            int grow = row0 + h * 8;
            if (grow >= M) continue;
            TOUT* crow = Cout + (size_t)grow * ldc + outColBase;
#pragma unroll
            for (int j = 0; j < NF; ++j) {
                int c = nBase + j * 8 + ((lane & 3) << 1);
                float vx = acc[i][j][h * 2 + 0] + bias[colBase + c];
                float vy = acc[i][j][h * 2 + 1] + bias[colBase + c + 1];
                if (sizeof(TOUT) == 2) {
                    *(uint32_t*)((__half*)crow + c) =
                        pack2h(__float2half_rn(vx), __float2half_rn(vy));
                } else {
                    float2 v2 = make_float2(vx, vy);
                    *(float2*)((float*)crow + c) = v2;
                }
            }
        }
    }
}

// ---------------- skip/FiLM init: O = relu(gamma_s * lin + beta_s) ---------
// C is fp16 now: each thread handles 4 cols (uint2 = 4 halves).
__global__ void skip_init_kernel()
{
    int i = blockIdx.x * blockDim.x + threadIdx.x;   // over N*32 quads
    int total = N_NODES * 32;
    if (i >= total) return;
    int row = i >> 5;
    int q   = (i & 31) << 2;
    const __half* base = &g_C[(size_t)row * NCOLS];
    __half2 l01 = *(const __half2*)(base + q);
    __half2 l23 = *(const __half2*)(base + q + 2);
    __half2 b01 = *(const __half2*)(base + 128 + q);
    __half2 b23 = *(const __half2*)(base + 128 + q + 2);
    __half2 g01 = *(const __half2*)(base + 256 + q);
    __half2 g23 = *(const __half2*)(base + 256 + q + 2);
    float2 lf0 = __half22float2(l01), lf1 = __half22float2(l23);
    float2 bf0 = __half22float2(b01), bf1 = __half22float2(b23);
    float2 gf0 = __half22float2(g01), gf1 = __half22float2(g23);
    float4 o;
    o.x = fmaxf(gf0.x * lf0.x + bf0.x, 0.0f);
    o.y = fmaxf(gf0.y * lf0.y + bf0.y, 0.0f);
    o.z = fmaxf(gf1.x * lf1.x + bf1.x, 0.0f);
    o.w = fmaxf(gf1.y * lf1.y + bf1.y, 0.0f);
    *reinterpret_cast<float4*>(&g_O[(size_t)row * 128 + q]) = o;
}

// ---------------- edge message pass: one warp per edge ----------------------
__global__ void edge_kernel(const int* __restrict__ ei, const int* __restrict__ et)
{
    int gthread = blockIdx.x * blockDim.x + threadIdx.x;
    int warp = gthread >> 5;
    int lane = gthread & 31;
    if (warp >= NEDGE) return;

    int src = ei[warp];
    int dst = ei[NEDGE + warp];
    int r   = et[warp];

    const __half* xl = &g_C[(size_t)src * NCOLS + 384 + r * 384];
    const __half* bg = &g_C[(size_t)dst * NCOLS + 384 + r * 384 + 128];
    int c = g_cnt[dst * NREL + r];
    float inv = 1.0f / (float)(c > 0 ? c : 1);
    float* o = &g_O[(size_t)dst * 128];

    int j = lane << 2;   // 4 cols per lane
    __half2 x01 = *(const __half2*)(xl + j);
    __half2 x23 = *(const __half2*)(xl + j + 2);
    __half2 b01 = *(const __half2*)(bg + j);
    __half2 b23 = *(const __half2*)(bg + j + 2);
    __half2 g01 = *(const __half2*)(bg + 128 + j);
    __half2 g23 = *(const __half2*)(bg + 128 + j + 2);
    float2 xf0 = __half22float2(x01), xf1 = __half22float2(x23);
    float2 bf0 = __half22float2(b01), bf1 = __half22float2(b23);
    float2 gf0 = __half22float2(g01), gf1 = __half22float2(g23);
    float4 v;
    v.x = fmaxf(gf0.x * xf0.x + bf0.x, 0.0f) * inv;
    v.y = fmaxf(gf0.y * xf0.y + bf0.y, 0.0f) * inv;
    v.z = fmaxf(gf1.x * xf1.x + bf1.x, 0.0f) * inv;
    v.w = fmaxf(gf1.y * xf1.y + bf1.y, 0.0f) * inv;
    red_add_v4(&o[j], v);
}

// ---------------- launch ------------------------------------------------------
extern "C" void kernel_launch(void* const* d_in, const int* in_sizes, int n_in,
                              void* d_out, int out_size)
{
    const float* x           = (const float*)d_in[0];
    const int*   ei          = (const int*)d_in[1];
    const int*   et          = (const int*)d_in[2];
    const float* lin_skip_w  = (const float*)d_in[3];
    const float* film_skip_w = (const float*)d_in[4];
    const float* lins_w      = (const float*)d_in[5];
    const float* films_w     = (const float*)d_in[6];
    const float* films_b     = (const float*)d_in[7];
    const float* linear1_w   = (const float*)d_in[8];
    const float* linear1_b   = (const float*)d_in[9];
    float*       out         = (float*)d_out;

    void *pC, *pO, *pXh, *pWh, *pBias;
    cudaGetSymbolAddress(&pC,   g_C);
    cudaGetSymbolAddress(&pO,   g_O);
    cudaGetSymbolAddress(&pXh,  g_xh);
    cudaGetSymbolAddress(&pWh,  g_Wh);
    cudaGetSymbolAddress(&pBias, g_biasv);

    const int SMEM_T128 = 128 * RSTRIDE + 128 * RSTRIDE;  // 69632
    cudaFuncSetAttribute((const void*)mma_gemm_kernel<128, false, __half>,
                         cudaFuncAttributeMaxDynamicSharedMemorySize, SMEM_T128);
    cudaFuncSetAttribute((const void*)mma_gemm_kernel<128, true, float>,
                         cudaFuncAttributeMaxDynamicSharedMemorySize, SMEM_T128);

    // 1. prep: x -> fp16; pack W^T fp16 + bias (incl. linear1)
    split_x_kernel<<<(N_NODES * DIM + 255) / 256, 256>>>(x);
    pack_wt_kernel<<<(NCOLSW * DIM + 255) / 256, 256>>>(
        lin_skip_w, film_skip_w, lins_w, films_w, films_b, linear1_w, linear1_b);

    // 2. zero counts, count edges per (dst, relation)
    zero_cnt_kernel<<<(N_NODES * NREL + 255) / 256, 256>>>();
    cnt_kernel<<<(NEDGE + 255) / 256, 256>>>(ei, et);

    // 3. fused node GEMM (HMMA fp16): C[N, 2304] (fp16) = x @ Wpack + bias
    {
        dim3 grid((N_NODES + 127) / 128, NCOLS / 128);
        mma_gemm_kernel<128, false, __half><<<grid, 256, SMEM_T128>>>(
            (const __half*)pXh, x, (const __half*)pWh, (const float*)pBias,
            (__half*)pC, NCOLS, 0, N_NODES);
    }

    // 4. skip/FiLM init of O
    skip_init_kernel<<<(N_NODES * 32 + 255) / 256, 256>>>();

    // 5. edge message pass (one warp per edge, red.v4 accumulation)
    {
        int threads = 256;
        int wpb = threads / 32;
        int blocks = (NEDGE + wpb - 1) / wpb;
        edge_kernel<<<blocks, threads>>>(ei, et);
    }

    // 6+7. final projection with fused exact GELU:
    //      out = gelu(O) @ linear1_w + linear1_b  (fp32 out)
    {
        dim3 grid((N_NODES + 127) / 128, 1);
        mma_gemm_kernel<128, true, float><<<grid, 256, SMEM_T128>>>(
            (const __half*)pXh, (const float*)pO, (const __half*)pWh,
            (const float*)pBias, out, 128, NCOLS, N_NODES);
    }
}

// round 10
// speedup vs baseline: 2.7833x; 1.0524x over previous
#include <cuda_runtime.h>
#include <cuda_fp16.h>
#include <math.h>
#include <stdint.h>

// Problem constants (fixed shapes)
#define N_NODES 100000
#define DIM     128
#define NEDGE   600000
#define NREL    5
#define NCOLS   2304          // 128 lin_skip + 256 film_skip + 5*(128 lins + 256 films)
#define NCOLSW  2432          // + 128 cols for linear1_w (final projection)

// ---------------- scratch (device globals; no allocation allowed) ----------
__device__ __half   g_C[(size_t)N_NODES * NCOLS]; // fused node-GEMM output (fp16)
__device__ float    g_O[(size_t)N_NODES * DIM];   // aggregated "out" (pre-GELU)
__device__ __half   g_xh[(size_t)N_NODES * DIM];  // x in fp16
__device__ __half   g_Wh[(size_t)NCOLSW * DIM];   // W^T fp16: [c][k]
__device__ float    g_biasv[NCOLSW];              // packed bias
__device__ int      g_cnt[N_NODES * NREL];        // per (dst, rel) edge count
__device__ int      g_off[N_NODES + 1];           // CSR offsets by dst
__device__ int      g_fill[N_NODES];              // scatter cursors
__device__ uint32_t g_elist[NEDGE];               // packed (src<<3)|r, dst-sorted

// ---------------- PTX helpers (base PTX only; no 'a' features) -------------
__device__ __forceinline__ uint32_t smem_u32(const void* p) {
    uint32_t a;
    asm("{ .reg .u64 t; cvta.to.shared.u64 t, %1; cvt.u32.u64 %0, t; }"
        : "=r"(a) : "l"(p));
    return a;
}
__device__ __forceinline__ void ldsm_x4(uint32_t (&r)[4], uint32_t addr) {
    asm volatile("ldmatrix.sync.aligned.m8n8.x4.shared.b16 {%0,%1,%2,%3}, [%4];"
                 : "=r"(r[0]), "=r"(r[1]), "=r"(r[2]), "=r"(r[3]) : "r"(addr));
}
__device__ __forceinline__ void mma16816(float (&d)[4], const uint32_t (&a)[4],
                                         const uint32_t (&b)[2]) {
    asm volatile(
        "mma.sync.aligned.m16n8k16.row.col.f32.f16.f16.f32 "
        "{%0,%1,%2,%3}, {%4,%5,%6,%7}, {%8,%9}, {%0,%1,%2,%3};"
        : "+f"(d[0]), "+f"(d[1]), "+f"(d[2]), "+f"(d[3])
        : "r"(a[0]), "r"(a[1]), "r"(a[2]), "r"(a[3]), "r"(b[0]), "r"(b[1]));
}
__device__ __forceinline__ uint32_t pack2h(__half a, __half b) {
    __half2 t = __halves2half2(a, b);
    return *reinterpret_cast<uint32_t*>(&t);
}

// ---------------- prep kernels ----------------------------------------------
__global__ void split_x_kernel(const float* __restrict__ x)
{
    int i = blockIdx.x * blockDim.x + threadIdx.x;
    if (i >= N_NODES * DIM) return;
    g_xh[i] = __float2half_rn(x[i]);
}

__global__ void pack_wt_kernel(const float* __restrict__ lin_skip_w,
                               const float* __restrict__ film_skip_w,
                               const float* __restrict__ lins_w,
                               const float* __restrict__ films_w,
                               const float* __restrict__ films_b,
                               const float* __restrict__ linear1_w,
                               const float* __restrict__ linear1_b)
{
    int idx = blockIdx.x * blockDim.x + threadIdx.x;   // over NCOLSW*128
    if (idx < NCOLSW * DIM) {
        int c = idx / DIM;
        int k = idx % DIM;
        float v;
        if (c < 128) {
            v = lin_skip_w[k * 128 + c];
        } else if (c < 384) {
            v = film_skip_w[k * 256 + (c - 128)];
        } else if (c < NCOLS) {
            int r  = (c - 384) / 384;
            int cc = (c - 384) % 384;
            if (cc < 128) v = lins_w[((size_t)r * 128 + k) * 128 + cc];
            else          v = films_w[((size_t)r * 128 + k) * 256 + (cc - 128)];
        } else {
            v = linear1_w[k * 128 + (c - NCOLS)];
        }
        g_Wh[idx] = __float2half_rn(v);
    }
    if (idx < NCOLSW) {
        float b = 0.0f;
        if (idx >= 384 && idx < NCOLS) {
            int r  = (idx - 384) / 384;
            int cc = (idx - 384) % 384;
            if (cc >= 128) b = films_b[r * 256 + (cc - 128)];
        } else if (idx >= NCOLS) {
            b = linear1_b[idx - NCOLS];
        }
        g_biasv[idx] = b;
    }
}

__global__ void zero_kernel()
{
    int i = blockIdx.x * blockDim.x + threadIdx.x;
    if (i < N_NODES * NREL) g_cnt[i] = 0;
    if (i < N_NODES) g_fill[i] = 0;
}

__global__ void cnt_kernel(const int* __restrict__ ei, const int* __restrict__ et)
{
    int e = blockIdx.x * blockDim.x + threadIdx.x;
    if (e < NEDGE) {
        int dst = ei[NEDGE + e];
        int r   = et[e];
        atomicAdd(&g_cnt[dst * NREL + r], 1);
    }
}

// single-block exclusive scan over per-dst degrees (sum of 5 cnt entries)
__global__ void __launch_bounds__(1024, 1)
scan_kernel()
{
    __shared__ int wsum[32];
    __shared__ int carry_s;
    int tid  = threadIdx.x;
    int lane = tid & 31;
    int wid  = tid >> 5;
    if (tid == 0) carry_s = 0;
    __syncthreads();

    for (int base = 0; base < N_NODES; base += 1024) {
        int d = base + tid;
        int v = 0;
        if (d < N_NODES) {
            const int* c = &g_cnt[d * NREL];
            v = c[0] + c[1] + c[2] + c[3] + c[4];
        }
        int orig = v;
        // inclusive warp scan
#pragma unroll
        for (int o = 1; o < 32; o <<= 1) {
            int t = __shfl_up_sync(0xFFFFFFFF, v, o);
            if (lane >= o) v += t;
        }
        if (lane == 31) wsum[wid] = v;
        __syncthreads();
        if (wid == 0) {
            int s = wsum[lane];
#pragma unroll
            for (int o = 1; o < 32; o <<= 1) {
                int t = __shfl_up_sync(0xFFFFFFFF, s, o);
                if (lane >= o) s += t;
            }
            wsum[lane] = s;
        }
        __syncthreads();
        int winc = (wid > 0) ? wsum[wid - 1] : 0;
        int excl = carry_s + winc + (v - orig);
        if (d < N_NODES) g_off[d] = excl;
        __syncthreads();
        if (tid == 0) carry_s += wsum[31];
        __syncthreads();
    }
    if (threadIdx.x == 0) g_off[N_NODES] = carry_s;
}

__global__ void scatter_kernel(const int* __restrict__ ei, const int* __restrict__ et)
{
    int e = blockIdx.x * blockDim.x + threadIdx.x;
    if (e >= NEDGE) return;
    int src = ei[e];
    int dst = ei[NEDGE + e];
    int r   = et[e];
    int pos = g_off[dst] + atomicAdd(&g_fill[dst], 1);
    g_elist[pos] = ((uint32_t)src << 3) | (uint32_t)r;
}

// ---------------- mma.sync GEMM (pure fp16, 512 threads, 32x32 warp tiles) --
// C[128 x TN] tile per CTA; whole K=128 resident in SMEM.
// SMEM = A 34816 + B 34816 = 69632 B -> 2 CTAs/SM (32 warps).
#define RSTRIDE 272

template <int TN, bool GELU, typename TOUT>
__global__ void __launch_bounds__(512, 2)
mma_gemm_kernel(const __half* __restrict__ Ah,
                const float* __restrict__ Af,
                const __half* __restrict__ W,
                const float* __restrict__ bias,
                TOUT* __restrict__ Cout, int ldc,
                int colBase0, int M)
{
    constexpr int NF = 4;   // 32 cols per warp tile
    extern __shared__ char smem[];
    uint32_t sb = smem_u32(smem);

    int tid  = threadIdx.x;
    int wid  = tid >> 5;
    int lane = tid & 31;
    int rowBase = blockIdx.x * 128;
    int colBase = colBase0 + blockIdx.y * TN;

    const uint32_t sB = 128 * RSTRIDE;   // 34816

    // ---- stage A ----
    if (!GELU) {
        for (int i = tid; i < 128 * 16; i += 512) {
            int row = i >> 4, ch = i & 15;
            int grow = rowBase + row;
            uint4 v = make_uint4(0, 0, 0, 0);
            if (grow < M)
                v = *(const uint4*)(Ah + (size_t)grow * DIM + ch * 8);
            *(uint4*)(smem + row * RSTRIDE + ch * 16) = v;
        }
    } else {
        for (int i = tid; i < 128 * 16; i += 512) {
            int row = i >> 4, ch = i & 15;
            int grow = rowBase + row;
            float v[8];
            if (grow < M) {
                float4 f0 = *(const float4*)(Af + (size_t)grow * DIM + ch * 8);
                float4 f1 = *(const float4*)(Af + (size_t)grow * DIM + ch * 8 + 4);
                v[0]=f0.x; v[1]=f0.y; v[2]=f0.z; v[3]=f0.w;
                v[4]=f1.x; v[5]=f1.y; v[6]=f1.z; v[7]=f1.w;
            } else {
#pragma unroll
                for (int j = 0; j < 8; ++j) v[j] = 0.0f;
            }
#pragma unroll
            for (int j = 0; j < 8; ++j)
                v[j] = 0.5f * v[j] * (1.0f + erff(v[j] * 0.70710678118654752f));
            uint4 uh;
            uh.x = pack2h(__float2half_rn(v[0]), __float2half_rn(v[1]));
            uh.y = pack2h(__float2half_rn(v[2]), __float2half_rn(v[3]));
            uh.z = pack2h(__float2half_rn(v[4]), __float2half_rn(v[5]));
            uh.w = pack2h(__float2half_rn(v[6]), __float2half_rn(v[7]));
            *(uint4*)(smem + row * RSTRIDE + ch * 16) = uh;
        }
    }
    // ---- stage B (fp16 W^T rows) ----
    for (int i = tid; i < TN * 16; i += 512) {
        int row = i >> 4, ch = i & 15;
        int gc = colBase + row;
        *(uint4*)(smem + sB + row * RSTRIDE + ch * 16) =
            *(const uint4*)(W + (size_t)gc * DIM + ch * 8);
    }
    __syncthreads();

    // 16 warps: 4x4 grid of 32x32 warp tiles
    int mBase = (wid >> 2) * 32;
    int nBase = (wid & 3) * 32;

    float acc[2][NF][4];
#pragma unroll
    for (int i = 0; i < 2; ++i)
#pragma unroll
        for (int j = 0; j < NF; ++j)
#pragma unroll
            for (int q = 0; q < 4; ++q) acc[i][j][q] = 0.0f;

    uint32_t aAddr = sb + (uint32_t)(mBase + (lane & 15)) * RSTRIDE
                   + (uint32_t)((lane >> 4) << 3) * 2;
    uint32_t bAddr = sb + sB
                   + (uint32_t)(nBase + (((lane >> 4) & 1) << 3) + (lane & 7)) * RSTRIDE
                   + (uint32_t)(((lane >> 3) & 1) << 3) * 2;

#pragma unroll
    for (int ks = 0; ks < 8; ++ks) {
        uint32_t b[NF][2];
#pragma unroll
        for (int jj = 0; jj < NF / 2; ++jj) {
            uint32_t r[4];
            ldsm_x4(r, bAddr + jj * 16 * RSTRIDE + ks * 32);
            b[2 * jj][0] = r[0]; b[2 * jj][1] = r[1];
            b[2 * jj + 1][0] = r[2]; b[2 * jj + 1][1] = r[3];
        }
        uint32_t a[2][4];
#pragma unroll
        for (int i = 0; i < 2; ++i)
            ldsm_x4(a[i], aAddr + i * 16 * RSTRIDE + ks * 32);
#pragma unroll
        for (int i = 0; i < 2; ++i)
#pragma unroll
            for (int j = 0; j < NF; ++j)
                mma16816(acc[i][j], a[i], b[j]);
    }

    // ---- epilogue: add bias (fp32), store (fp16 or fp32) ----
    int outColBase = colBase - colBase0;
#pragma unroll
    for (int i = 0; i < 2; ++i) {
        int row0 = rowBase + mBase + i * 16 + (lane >> 2);
#pragma unroll
        for (int h = 0; h < 2; ++h) {
            int grow = row0 + h * 8;
            if (grow >= M) continue;
            TOUT* crow = Cout + (size_t)grow * ldc + outColBase;
#pragma unroll
            for (int j = 0; j < NF; ++j) {
                int c = nBase + j * 8 + ((lane & 3) << 1);
                float vx = acc[i][j][h * 2 + 0] + bias[colBase + c];
                float vy = acc[i][j][h * 2 + 1] + bias[colBase + c + 1];
                if (sizeof(TOUT) == 2) {
                    *(uint32_t*)((__half*)crow + c) =
                        pack2h(__float2half_rn(vx), __float2half_rn(vy));
                } else {
                    float2 v2 = make_float2(vx, vy);
                    *(float2*)((float*)crow + c) = v2;
                }
            }
        }
    }
}

// ---------------- aggregation: one warp per dst -----------------------------
// O[d] = relu(gamma_s*lin + beta_s)  +  sum_{edges e->d} relu(g*xl[src]+b)/cnt
__global__ void __launch_bounds__(256)
agg_kernel()
{
    int gwarp = (blockIdx.x * blockDim.x + threadIdx.x) >> 5;
    int lane  = threadIdx.x & 31;
    if (gwarp >= N_NODES) return;
    int d = gwarp;
    int j = lane << 2;   // 4 cols per lane

    const __half* base = &g_C[(size_t)d * NCOLS];

    // skip part
    __half2 l01 = *(const __half2*)(base + j);
    __half2 l23 = *(const __half2*)(base + j + 2);
    __half2 b01 = *(const __half2*)(base + 128 + j);
    __half2 b23 = *(const __half2*)(base + 128 + j + 2);
    __half2 s01 = *(const __half2*)(base + 256 + j);
    __half2 s23 = *(const __half2*)(base + 256 + j + 2);
    float2 lf0 = __half22float2(l01), lf1 = __half22float2(l23);
    float2 bf0 = __half22float2(b01), bf1 = __half22float2(b23);
    float2 gf0 = __half22float2(s01), gf1 = __half22float2(s23);
    float4 acc;
    acc.x = fmaxf(gf0.x * lf0.x + bf0.x, 0.0f);
    acc.y = fmaxf(gf0.y * lf0.y + bf0.y, 0.0f);
    acc.z = fmaxf(gf1.x * lf1.x + bf1.x, 0.0f);
    acc.w = fmaxf(gf1.y * lf1.y + bf1.y, 0.0f);

    int begin = g_off[d];
    int end   = g_off[d + 1];
    for (int e = begin; e < end; ++e) {
        uint32_t packed = g_elist[e];
        int src = packed >> 3;
        int r   = packed & 7;
        const __half* cb = &g_C[(size_t)src * NCOLS + 384 + r * 384];        // xl
        const __half* db = &g_C[(size_t)d   * NCOLS + 384 + r * 384 + 128];  // beta; +128 gamma
        int c = g_cnt[d * NREL + r];
        float inv = 1.0f / (float)(c > 0 ? c : 1);
        __half2 x01 = *(const __half2*)(cb + j);
        __half2 x23 = *(const __half2*)(cb + j + 2);
        __half2 eb01 = *(const __half2*)(db + j);
        __half2 eb23 = *(const __half2*)(db + j + 2);
        __half2 eg01 = *(const __half2*)(db + 128 + j);
        __half2 eg23 = *(const __half2*)(db + 128 + j + 2);
        float2 xf0 = __half22float2(x01), xf1 = __half22float2(x23);
        float2 ebf0 = __half22float2(eb01), ebf1 = __half22float2(eb23);
        float2 egf0 = __half22float2(eg01), egf1 = __half22float2(eg23);
        acc.x += fmaxf(egf0.x * xf0.x + ebf0.x, 0.0f) * inv;
        acc.y += fmaxf(egf0.y * xf0.y + ebf0.y, 0.0f) * inv;
        acc.z += fmaxf(egf1.x * xf1.x + ebf1.x, 0.0f) * inv;
        acc.w += fmaxf(egf1.y * xf1.y + ebf1.y, 0.0f) * inv;
    }
    *reinterpret_cast<float4*>(&g_O[(size_t)d * 128 + j]) = acc;
}

// ---------------- launch ------------------------------------------------------
extern "C" void kernel_launch(void* const* d_in, const int* in_sizes, int n_in,
                              void* d_out, int out_size)
{
    const float* x           = (const float*)d_in[0];
    const int*   ei          = (const int*)d_in[1];
    const int*   et          = (const int*)d_in[2];
    const float* lin_skip_w  = (const float*)d_in[3];
    const float* film_skip_w = (const float*)d_in[4];
    const float* lins_w      = (const float*)d_in[5];
    const float* films_w     = (const float*)d_in[6];
    const float* films_b     = (const float*)d_in[7];
    const float* linear1_w   = (const float*)d_in[8];
    const float* linear1_b   = (const float*)d_in[9];
    float*       out         = (float*)d_out;

    void *pC, *pO, *pXh, *pWh, *pBias;
    cudaGetSymbolAddress(&pC,   g_C);
    cudaGetSymbolAddress(&pO,   g_O);
    cudaGetSymbolAddress(&pXh,  g_xh);
    cudaGetSymbolAddress(&pWh,  g_Wh);
    cudaGetSymbolAddress(&pBias, g_biasv);

    const int SMEM_T128 = 128 * RSTRIDE + 128 * RSTRIDE;  // 69632
    cudaFuncSetAttribute((const void*)mma_gemm_kernel<128, false, __half>,
                         cudaFuncAttributeMaxDynamicSharedMemorySize, SMEM_T128);
    cudaFuncSetAttribute((const void*)mma_gemm_kernel<128, true, float>,
                         cudaFuncAttributeMaxDynamicSharedMemorySize, SMEM_T128);

    // 1. prep: x -> fp16; pack W^T fp16 + bias (incl. linear1)
    split_x_kernel<<<(N_NODES * DIM + 255) / 256, 256>>>(x);
    pack_wt_kernel<<<(NCOLSW * DIM + 255) / 256, 256>>>(
        lin_skip_w, film_skip_w, lins_w, films_w, films_b, linear1_w, linear1_b);

    // 2. edge indexing: counts -> offsets -> dst-sorted packed list
    zero_kernel<<<(N_NODES * NREL + 255) / 256, 256>>>();
    cnt_kernel<<<(NEDGE + 255) / 256, 256>>>(ei, et);
    scan_kernel<<<1, 1024>>>();
    scatter_kernel<<<(NEDGE + 255) / 256, 256>>>(ei, et);

    // 3. fused node GEMM (HMMA fp16): C[N, 2304] (fp16) = x @ Wpack + bias
    {
        dim3 grid((N_NODES + 127) / 128, NCOLS / 128);
        mma_gemm_kernel<128, false, __half><<<grid, 512, SMEM_T128>>>(
            (const __half*)pXh, x, (const __half*)pWh, (const float*)pBias,
            (__half*)pC, NCOLS, 0, N_NODES);
    }

    // 4. aggregation (skip + messages), atomics-free
    {
        int warps_per_block = 256 / 32;
        int blocks = (N_NODES + warps_per_block - 1) / warps_per_block;
        agg_kernel<<<blocks, 256>>>();
    }

    // 5. final projection with fused exact GELU:
    //    out = gelu(O) @ linear1_w + linear1_b  (fp32 out)
    {
        dim3 grid((N_NODES + 127) / 128, 1);
        mma_gemm_kernel<128, true, float><<<grid, 512, SMEM_T128>>>(
            (const __half*)pXh, (const float*)pO, (const __half*)pWh,
            (const float*)pBias, out, 128, NCOLS, N_NODES);
    }
}

// round 11
// speedup vs baseline: 3.0532x; 1.0970x over previous
#include <cuda_runtime.h>
#include <cuda_fp16.h>
#include <math.h>
#include <stdint.h>

// Problem constants (fixed shapes)
#define N_NODES 100000
#define DIM     128
#define NEDGE   600000
#define NREL    5
#define NCOLS   2304          // 128 lin_skip + 256 film_skip + 5*(128 lins + 256 films)
#define NCOLSW  2432          // + 128 cols for linear1_w (final projection)
#define NBINS   (N_NODES * NREL)
#define NBLK_SCAN ((NBINS + 1023) / 1024)   // 489

// ---------------- scratch (device globals; no allocation allowed) ----------
__device__ __half   g_C[(size_t)N_NODES * NCOLS]; // fused node-GEMM output (fp16)
__device__ __half   g_xh[(size_t)N_NODES * DIM];  // x fp16; later gelu(out) fp16
__device__ __half   g_Wh[(size_t)NCOLSW * DIM];   // W^T fp16: [c][k]
__device__ float    g_biasv[NCOLSW];              // packed bias
__device__ int      g_cnt[NBINS];                 // per (dst, rel) edge count
__device__ int      g_off[NBINS + 1];             // CSR offsets by (dst, rel)
__device__ int      g_fill[NBINS];                // scatter cursors
__device__ int      g_bsum[512];                  // scan block sums
__device__ int      g_elist[NEDGE];               // src ids, (dst,rel)-sorted

// ---------------- PTX helpers (base PTX only; no 'a' features) -------------
__device__ __forceinline__ uint32_t smem_u32(const void* p) {
    uint32_t a;
    asm("{ .reg .u64 t; cvta.to.shared.u64 t, %1; cvt.u32.u64 %0, t; }"
        : "=r"(a) : "l"(p));
    return a;
}
__device__ __forceinline__ void ldsm_x4(uint32_t (&r)[4], uint32_t addr) {
    asm volatile("ldmatrix.sync.aligned.m8n8.x4.shared.b16 {%0,%1,%2,%3}, [%4];"
                 : "=r"(r[0]), "=r"(r[1]), "=r"(r[2]), "=r"(r[3]) : "r"(addr));
}
__device__ __forceinline__ void mma16816(float (&d)[4], const uint32_t (&a)[4],
                                         const uint32_t (&b)[2]) {
    asm volatile(
        "mma.sync.aligned.m16n8k16.row.col.f32.f16.f16.f32 "
        "{%0,%1,%2,%3}, {%4,%5,%6,%7}, {%8,%9}, {%0,%1,%2,%3};"
        : "+f"(d[0]), "+f"(d[1]), "+f"(d[2]), "+f"(d[3])
        : "r"(a[0]), "r"(a[1]), "r"(a[2]), "r"(a[3]), "r"(b[0]), "r"(b[1]));
}
__device__ __forceinline__ uint32_t pack2h(__half a, __half b) {
    __half2 t = __halves2half2(a, b);
    return *reinterpret_cast<uint32_t*>(&t);
}

// ---------------- prep kernels ----------------------------------------------
__global__ void split_x_kernel(const float* __restrict__ x)
{
    int i = blockIdx.x * blockDim.x + threadIdx.x;
    if (i >= N_NODES * DIM) return;
    g_xh[i] = __float2half_rn(x[i]);
}

__global__ void pack_wt_kernel(const float* __restrict__ lin_skip_w,
                               const float* __restrict__ film_skip_w,
                               const float* __restrict__ lins_w,
                               const float* __restrict__ films_w,
                               const float* __restrict__ films_b,
                               const float* __restrict__ linear1_w,
                               const float* __restrict__ linear1_b)
{
    int idx = blockIdx.x * blockDim.x + threadIdx.x;   // over NCOLSW*128
    if (idx < NCOLSW * DIM) {
        int c = idx / DIM;
        int k = idx % DIM;
        float v;
        if (c < 128) {
            v = lin_skip_w[k * 128 + c];
        } else if (c < 384) {
            v = film_skip_w[k * 256 + (c - 128)];
        } else if (c < NCOLS) {
            int r  = (c - 384) / 384;
            int cc = (c - 384) % 384;
            if (cc < 128) v = lins_w[((size_t)r * 128 + k) * 128 + cc];
            else          v = films_w[((size_t)r * 128 + k) * 256 + (cc - 128)];
        } else {
            v = linear1_w[k * 128 + (c - NCOLS)];
        }
        g_Wh[idx] = __float2half_rn(v);
    }
    if (idx < NCOLSW) {
        float b = 0.0f;
        if (idx >= 384 && idx < NCOLS) {
            int r  = (idx - 384) / 384;
            int cc = (idx - 384) % 384;
            if (cc >= 128) b = films_b[r * 256 + (cc - 128)];
        } else if (idx >= NCOLS) {
            b = linear1_b[idx - NCOLS];
        }
        g_biasv[idx] = b;
    }
}

__global__ void zero_kernel()
{
    int i = blockIdx.x * blockDim.x + threadIdx.x;
    if (i < NBINS) { g_cnt[i] = 0; g_fill[i] = 0; }
}

__global__ void cnt_kernel(const int* __restrict__ ei, const int* __restrict__ et)
{
    int e = blockIdx.x * blockDim.x + threadIdx.x;
    if (e < NEDGE) {
        int dst = ei[NEDGE + e];
        int r   = et[e];
        atomicAdd(&g_cnt[dst * NREL + r], 1);
    }
}

// ---- 3-phase parallel exclusive scan over g_cnt (NBINS entries) ----
__global__ void __launch_bounds__(1024)
scan1_kernel()
{
    __shared__ int wsum[32];
    int tid  = threadIdx.x;
    int lane = tid & 31;
    int wid  = tid >> 5;
    int idx  = blockIdx.x * 1024 + tid;
    int v = (idx < NBINS) ? g_cnt[idx] : 0;
    int orig = v;
#pragma unroll
    for (int o = 1; o < 32; o <<= 1) {
        int t = __shfl_up_sync(0xFFFFFFFF, v, o);
        if (lane >= o) v += t;
    }
    if (lane == 31) wsum[wid] = v;
    __syncthreads();
    if (wid == 0) {
        int s = wsum[lane];
#pragma unroll
        for (int o = 1; o < 32; o <<= 1) {
            int t = __shfl_up_sync(0xFFFFFFFF, s, o);
            if (lane >= o) s += t;
        }
        wsum[lane] = s;
    }
    __syncthreads();
    int winc = (wid > 0) ? wsum[wid - 1] : 0;
    if (idx < NBINS) g_off[idx] = winc + (v - orig);
    if (tid == 1023) g_bsum[blockIdx.x] = winc + v;
}

__global__ void __launch_bounds__(512)
scan2_kernel()
{
    __shared__ int wsum[16];
    int tid  = threadIdx.x;
    int lane = tid & 31;
    int wid  = tid >> 5;
    int v = (tid < NBLK_SCAN) ? g_bsum[tid] : 0;
    int orig = v;
#pragma unroll
    for (int o = 1; o < 32; o <<= 1) {
        int t = __shfl_up_sync(0xFFFFFFFF, v, o);
        if (lane >= o) v += t;
    }
    if (lane == 31) wsum[wid] = v;
    __syncthreads();
    if (wid == 0 && lane < 16) {
        int s = wsum[lane];
#pragma unroll
        for (int o = 1; o < 16; o <<= 1) {
            int t = __shfl_up_sync(0xFFFF, s, o);
            if (lane >= o) s += t;
        }
        wsum[lane] = s;
    }
    __syncthreads();
    int winc = (wid > 0) ? wsum[wid - 1] : 0;
    if (tid < NBLK_SCAN) g_bsum[tid] = winc + (v - orig);
}

__global__ void __launch_bounds__(1024)
scan3_kernel()
{
    int idx = blockIdx.x * 1024 + threadIdx.x;
    if (idx < NBINS) g_off[idx] += g_bsum[blockIdx.x];
    if (idx == 0) g_off[NBINS] = NEDGE;
}

__global__ void scatter_kernel(const int* __restrict__ ei, const int* __restrict__ et)
{
    int e = blockIdx.x * blockDim.x + threadIdx.x;
    if (e >= NEDGE) return;
    int src = ei[e];
    int dst = ei[NEDGE + e];
    int r   = et[e];
    int bin = dst * NREL + r;
    int pos = g_off[bin] + atomicAdd(&g_fill[bin], 1);
    g_elist[pos] = src;
}

// ---------------- mma.sync GEMM (pure fp16, 512 threads, 32x32 warp tiles) --
#define RSTRIDE 272

template <int TN, typename TOUT>
__global__ void __launch_bounds__(512, 2)
mma_gemm_kernel(const __half* __restrict__ Ah,
                const __half* __restrict__ W,
                const float* __restrict__ bias,
                TOUT* __restrict__ Cout, int ldc,
                int colBase0, int M)
{
    constexpr int NF = 4;   // 32 cols per warp tile
    extern __shared__ char smem[];
    uint32_t sb = smem_u32(smem);

    int tid  = threadIdx.x;
    int wid  = tid >> 5;
    int lane = tid & 31;
    int rowBase = blockIdx.x * 128;
    int colBase = colBase0 + blockIdx.y * TN;

    const uint32_t sB = 128 * RSTRIDE;   // 34816

    // ---- stage A (fp16 rows) ----
    for (int i = tid; i < 128 * 16; i += 512) {
        int row = i >> 4, ch = i & 15;
        int grow = rowBase + row;
        uint4 v = make_uint4(0, 0, 0, 0);
        if (grow < M)
            v = *(const uint4*)(Ah + (size_t)grow * DIM + ch * 8);
        *(uint4*)(smem + row * RSTRIDE + ch * 16) = v;
    }
    // ---- stage B (fp16 W^T rows) ----
    for (int i = tid; i < TN * 16; i += 512) {
        int row = i >> 4, ch = i & 15;
        int gc = colBase + row;
        *(uint4*)(smem + sB + row * RSTRIDE + ch * 16) =
            *(const uint4*)(W + (size_t)gc * DIM + ch * 8);
    }
    __syncthreads();

    // 16 warps: 4x4 grid of 32x32 warp tiles
    int mBase = (wid >> 2) * 32;
    int nBase = (wid & 3) * 32;

    float acc[2][NF][4];
#pragma unroll
    for (int i = 0; i < 2; ++i)
#pragma unroll
        for (int j = 0; j < NF; ++j)
#pragma unroll
            for (int q = 0; q < 4; ++q) acc[i][j][q] = 0.0f;

    uint32_t aAddr = sb + (uint32_t)(mBase + (lane & 15)) * RSTRIDE
                   + (uint32_t)((lane >> 4) << 3) * 2;
    uint32_t bAddr = sb + sB
                   + (uint32_t)(nBase + (((lane >> 4) & 1) << 3) + (lane & 7)) * RSTRIDE
                   + (uint32_t)(((lane >> 3) & 1) << 3) * 2;

#pragma unroll
    for (int ks = 0; ks < 8; ++ks) {
        uint32_t b[NF][2];
#pragma unroll
        for (int jj = 0; jj < NF / 2; ++jj) {
            uint32_t r[4];
            ldsm_x4(r, bAddr + jj * 16 * RSTRIDE + ks * 32);
            b[2 * jj][0] = r[0]; b[2 * jj][1] = r[1];
            b[2 * jj + 1][0] = r[2]; b[2 * jj + 1][1] = r[3];
        }
        uint32_t a[2][4];
#pragma unroll
        for (int i = 0; i < 2; ++i)
            ldsm_x4(a[i], aAddr + i * 16 * RSTRIDE + ks * 32);
#pragma unroll
        for (int i = 0; i < 2; ++i)
#pragma unroll
            for (int j = 0; j < NF; ++j)
                mma16816(acc[i][j], a[i], b[j]);
    }

    // ---- epilogue: add bias (fp32), store ----
    int outColBase = colBase - colBase0;
#pragma unroll
    for (int i = 0; i < 2; ++i) {
        int row0 = rowBase + mBase + i * 16 + (lane >> 2);
#pragma unroll
        for (int h = 0; h < 2; ++h) {
            int grow = row0 + h * 8;
            if (grow >= M) continue;
            TOUT* crow = Cout + (size_t)grow * ldc + outColBase;
#pragma unroll
            for (int j = 0; j < NF; ++j) {
                int c = nBase + j * 8 + ((lane & 3) << 1);
                float vx = acc[i][j][h * 2 + 0] + bias[colBase + c];
                float vy = acc[i][j][h * 2 + 1] + bias[colBase + c + 1];
                if (sizeof(TOUT) == 2) {
                    *(uint32_t*)((__half*)crow + c) =
                        pack2h(__float2half_rn(vx), __float2half_rn(vy));
                } else {
                    float2 v2 = make_float2(vx, vy);
                    *(float2*)((float*)crow + c) = v2;
                }
            }
        }
    }
}

// ---------------- aggregation: one warp per dst, binned by relation ---------
// acc = relu(gamma_s*lin + beta_s) + sum_r inv_r * sum_e relu(g_r*xl[src]+b_r)
// then gelu(acc) -> fp16 into g_xh (overwrites x; GEMM already consumed it)
__global__ void __launch_bounds__(256)
agg_kernel()
{
    int gwarp = (blockIdx.x * blockDim.x + threadIdx.x) >> 5;
    int lane  = threadIdx.x & 31;
    if (gwarp >= N_NODES) return;
    int d = gwarp;
    int j = lane << 2;   // 4 cols per lane

    const __half* base = &g_C[(size_t)d * NCOLS];

    // skip part
    __half2 l01 = *(const __half2*)(base + j);
    __half2 l23 = *(const __half2*)(base + j + 2);
    __half2 b01 = *(const __half2*)(base + 128 + j);
    __half2 b23 = *(const __half2*)(base + 128 + j + 2);
    __half2 s01 = *(const __half2*)(base + 256 + j);
    __half2 s23 = *(const __half2*)(base + 256 + j + 2);
    float2 lf0 = __half22float2(l01), lf1 = __half22float2(l23);
    float2 bf0 = __half22float2(b01), bf1 = __half22float2(b23);
    float2 gf0 = __half22float2(s01), gf1 = __half22float2(s23);
    float4 acc;
    acc.x = fmaxf(gf0.x * lf0.x + bf0.x, 0.0f);
    acc.y = fmaxf(gf0.y * lf0.y + bf0.y, 0.0f);
    acc.z = fmaxf(gf1.x * lf1.x + bf1.x, 0.0f);
    acc.w = fmaxf(gf1.y * lf1.y + bf1.y, 0.0f);

#pragma unroll
    for (int r = 0; r < NREL; ++r) {
        int begin = g_off[d * NREL + r];
        int end   = g_off[d * NREL + r + 1];
        if (begin == end) continue;
        // hoist beta/gamma for this (dst, rel)
        const __half* db = base + 384 + r * 384 + 128;
        __half2 eb01 = *(const __half2*)(db + j);
        __half2 eb23 = *(const __half2*)(db + j + 2);
        __half2 eg01 = *(const __half2*)(db + 128 + j);
        __half2 eg23 = *(const __half2*)(db + 128 + j + 2);
        float2 ebf0 = __half22float2(eb01), ebf1 = __half22float2(eb23);
        float2 egf0 = __half22float2(eg01), egf1 = __half22float2(eg23);
        float inv = 1.0f / (float)(end - begin);
        float4 racc = make_float4(0.f, 0.f, 0.f, 0.f);
        const size_t xlOff = 384 + (size_t)r * 384;
        for (int e = begin; e < end; ++e) {
            int src = g_elist[e];
            const __half* cb = &g_C[(size_t)src * NCOLS + xlOff];
            __half2 x01 = *(const __half2*)(cb + j);
            __half2 x23 = *(const __half2*)(cb + j + 2);
            float2 xf0 = __half22float2(x01), xf1 = __half22float2(x23);
            racc.x += fmaxf(egf0.x * xf0.x + ebf0.x, 0.0f);
            racc.y += fmaxf(egf0.y * xf0.y + ebf0.y, 0.0f);
            racc.z += fmaxf(egf1.x * xf1.x + ebf1.x, 0.0f);
            racc.w += fmaxf(egf1.y * xf1.y + ebf1.y, 0.0f);
        }
        acc.x += racc.x * inv;
        acc.y += racc.y * inv;
        acc.z += racc.z * inv;
        acc.w += racc.w * inv;
    }

    // exact GELU, store fp16 into g_xh
    const float kk = 0.70710678118654752f;
    acc.x = 0.5f * acc.x * (1.0f + erff(acc.x * kk));
    acc.y = 0.5f * acc.y * (1.0f + erff(acc.y * kk));
    acc.z = 0.5f * acc.z * (1.0f + erff(acc.z * kk));
    acc.w = 0.5f * acc.w * (1.0f + erff(acc.w * kk));
    uint2 hv;
    hv.x = pack2h(__float2half_rn(acc.x), __float2half_rn(acc.y));
    hv.y = pack2h(__float2half_rn(acc.z), __float2half_rn(acc.w));
    *reinterpret_cast<uint2*>(&g_xh[(size_t)d * DIM + j]) = hv;
}

// ---------------- launch ------------------------------------------------------
extern "C" void kernel_launch(void* const* d_in, const int* in_sizes, int n_in,
                              void* d_out, int out_size)
{
    const float* x           = (const float*)d_in[0];
    const int*   ei          = (const int*)d_in[1];
    const int*   et          = (const int*)d_in[2];
    const float* lin_skip_w  = (const float*)d_in[3];
    const float* film_skip_w = (const float*)d_in[4];
    const float* lins_w      = (const float*)d_in[5];
    const float* films_w     = (const float*)d_in[6];
    const float* films_b     = (const float*)d_in[7];
    const float* linear1_w   = (const float*)d_in[8];
    const float* linear1_b   = (const float*)d_in[9];
    float*       out         = (float*)d_out;

    void *pC, *pXh, *pWh, *pBias;
    cudaGetSymbolAddress(&pC,   g_C);
    cudaGetSymbolAddress(&pXh,  g_xh);
    cudaGetSymbolAddress(&pWh,  g_Wh);
    cudaGetSymbolAddress(&pBias, g_biasv);

    const int SMEM_T128 = 128 * RSTRIDE + 128 * RSTRIDE;  // 69632
    cudaFuncSetAttribute((const void*)mma_gemm_kernel<128, __half>,
                         cudaFuncAttributeMaxDynamicSharedMemorySize, SMEM_T128);
    cudaFuncSetAttribute((const void*)mma_gemm_kernel<128, float>,
                         cudaFuncAttributeMaxDynamicSharedMemorySize, SMEM_T128);

    // 1. prep: x -> fp16; pack W^T fp16 + bias (incl. linear1)
    split_x_kernel<<<(N_NODES * DIM + 255) / 256, 256>>>(x);
    pack_wt_kernel<<<(NCOLSW * DIM + 255) / 256, 256>>>(
        lin_skip_w, film_skip_w, lins_w, films_w, films_b, linear1_w, linear1_b);

    // 2. edge indexing: counts -> parallel scan -> (dst,rel)-sorted src list
    zero_kernel<<<(NBINS + 255) / 256, 256>>>();
    cnt_kernel<<<(NEDGE + 255) / 256, 256>>>(ei, et);
    scan1_kernel<<<NBLK_SCAN, 1024>>>();
    scan2_kernel<<<1, 512>>>();
    scan3_kernel<<<NBLK_SCAN, 1024>>>();
    scatter_kernel<<<(NEDGE + 255) / 256, 256>>>(ei, et);

    // 3. fused node GEMM (HMMA fp16): C[N, 2304] (fp16) = x @ Wpack + bias
    {
        dim3 grid((N_NODES + 127) / 128, NCOLS / 128);
        mma_gemm_kernel<128, __half><<<grid, 512, SMEM_T128>>>(
            (const __half*)pXh, (const __half*)pWh, (const float*)pBias,
            (__half*)pC, NCOLS, 0, N_NODES);
    }

    // 4. aggregation (skip + messages + GELU), atomics-free -> g_xh fp16
    {
        int warps_per_block = 256 / 32;
        int blocks = (N_NODES + warps_per_block - 1) / warps_per_block;
        agg_kernel<<<blocks, 256>>>();
    }

    // 5. final projection: out = gelu(O) @ linear1_w + linear1_b (fp32 out)
    {
        dim3 grid((N_NODES + 127) / 128, 1);
        mma_gemm_kernel<128, float><<<grid, 512, SMEM_T128>>>(
            (const __half*)pXh, (const __half*)pWh, (const float*)pBias,
            out, 128, NCOLS, N_NODES);
    }
}

// round 12
// speedup vs baseline: 3.1500x; 1.0317x over previous
#include <cuda_runtime.h>
#include <cuda_fp16.h>
#include <math.h>
#include <stdint.h>

// Problem constants (fixed shapes)
#define N_NODES 100000
#define DIM     128
#define NEDGE   600000
#define NREL    5
#define NCOLS   2304          // 128 lin_skip + 256 film_skip + 5*(128 lins + 256 films)
#define NCOLSW  2432          // + 128 cols for linear1_w (final projection)
#define NBINS   (N_NODES * NREL)
#define NBLK_SCAN ((NBINS + 1023) / 1024)   // 489
#define NCT     18            // column tiles in main GEMM

// ---------------- scratch (device globals; no allocation allowed) ----------
__device__ __half   g_C[(size_t)N_NODES * NCOLS]; // fused node-GEMM output (fp16)
__device__ __half   g_xh[(size_t)N_NODES * DIM];  // x fp16; later gelu(out) fp16
__device__ __half   g_Wh[(size_t)NCOLSW * DIM];   // W^T fp16: [c][k]
__device__ float    g_biasv[NCOLSW];              // packed bias
__device__ int      g_cnt[NBINS];                 // per (dst, rel) edge count
__device__ int      g_off[NBINS + 1];             // CSR offsets by (dst, rel)
__device__ int      g_fill[NBINS];                // scatter cursors
__device__ int      g_bsum[512];                  // scan block sums
__device__ int      g_elist[NEDGE];               // src ids, (dst,rel)-sorted

// ---------------- PTX helpers (base PTX only; no 'a' features) -------------
__device__ __forceinline__ uint32_t smem_u32(const void* p) {
    uint32_t a;
    asm("{ .reg .u64 t; cvta.to.shared.u64 t, %1; cvt.u32.u64 %0, t; }"
        : "=r"(a) : "l"(p));
    return a;
}
__device__ __forceinline__ void ldsm_x4(uint32_t (&r)[4], uint32_t addr) {
    asm volatile("ldmatrix.sync.aligned.m8n8.x4.shared.b16 {%0,%1,%2,%3}, [%4];"
                 : "=r"(r[0]), "=r"(r[1]), "=r"(r[2]), "=r"(r[3]) : "r"(addr));
}
__device__ __forceinline__ void mma16816(float (&d)[4], const uint32_t (&a)[4],
                                         const uint32_t (&b)[2]) {
    asm volatile(
        "mma.sync.aligned.m16n8k16.row.col.f32.f16.f16.f32 "
        "{%0,%1,%2,%3}, {%4,%5,%6,%7}, {%8,%9}, {%0,%1,%2,%3};"
        : "+f"(d[0]), "+f"(d[1]), "+f"(d[2]), "+f"(d[3])
        : "r"(a[0]), "r"(a[1]), "r"(a[2]), "r"(a[3]), "r"(b[0]), "r"(b[1]));
}
__device__ __forceinline__ uint32_t pack2h(__half a, __half b) {
    __half2 t = __halves2half2(a, b);
    return *reinterpret_cast<uint32_t*>(&t);
}
__device__ __forceinline__ void cp_async16(uint32_t dst, const void* src) {
    asm volatile("cp.async.cg.shared.global [%0], [%1], 16;"
                 :: "r"(dst), "l"(src) : "memory");
}
__device__ __forceinline__ void cp_commit() {
    asm volatile("cp.async.commit_group;" ::: "memory");
}
template <int N>
__device__ __forceinline__ void cp_wait() {
    asm volatile("cp.async.wait_group %0;" :: "n"(N) : "memory");
}

// ---------------- prep kernels ----------------------------------------------
__global__ void split_x_kernel(const float* __restrict__ x)
{
    int i = blockIdx.x * blockDim.x + threadIdx.x;
    if (i >= N_NODES * DIM) return;
    g_xh[i] = __float2half_rn(x[i]);
}

__global__ void pack_wt_kernel(const float* __restrict__ lin_skip_w,
                               const float* __restrict__ film_skip_w,
                               const float* __restrict__ lins_w,
                               const float* __restrict__ films_w,
                               const float* __restrict__ films_b,
                               const float* __restrict__ linear1_w,
                               const float* __restrict__ linear1_b)
{
    int idx = blockIdx.x * blockDim.x + threadIdx.x;   // over NCOLSW*128
    if (idx < NCOLSW * DIM) {
        int c = idx / DIM;
        int k = idx % DIM;
        float v;
        if (c < 128) {
            v = lin_skip_w[k * 128 + c];
        } else if (c < 384) {
            v = film_skip_w[k * 256 + (c - 128)];
        } else if (c < NCOLS) {
            int r  = (c - 384) / 384;
            int cc = (c - 384) % 384;
            if (cc < 128) v = lins_w[((size_t)r * 128 + k) * 128 + cc];
            else          v = films_w[((size_t)r * 128 + k) * 256 + (cc - 128)];
        } else {
            v = linear1_w[k * 128 + (c - NCOLS)];
        }
        g_Wh[idx] = __float2half_rn(v);
    }
    if (idx < NCOLSW) {
        float b = 0.0f;
        if (idx >= 384 && idx < NCOLS) {
            int r  = (idx - 384) / 384;
            int cc = (idx - 384) % 384;
            if (cc >= 128) b = films_b[r * 256 + (cc - 128)];
        } else if (idx >= NCOLS) {
            b = linear1_b[idx - NCOLS];
        }
        g_biasv[idx] = b;
    }
}

__global__ void zero_kernel()
{
    int i = blockIdx.x * blockDim.x + threadIdx.x;
    if (i < NBINS) { g_cnt[i] = 0; g_fill[i] = 0; }
}

__global__ void cnt_kernel(const int* __restrict__ ei, const int* __restrict__ et)
{
    int e = blockIdx.x * blockDim.x + threadIdx.x;
    if (e < NEDGE) {
        int dst = ei[NEDGE + e];
        int r   = et[e];
        atomicAdd(&g_cnt[dst * NREL + r], 1);
    }
}

// ---- 3-phase parallel exclusive scan over g_cnt ----
__global__ void __launch_bounds__(1024)
scan1_kernel()
{
    __shared__ int wsum[32];
    int tid  = threadIdx.x;
    int lane = tid & 31;
    int wid  = tid >> 5;
    int idx  = blockIdx.x * 1024 + tid;
    int v = (idx < NBINS) ? g_cnt[idx] : 0;
    int orig = v;
#pragma unroll
    for (int o = 1; o < 32; o <<= 1) {
        int t = __shfl_up_sync(0xFFFFFFFF, v, o);
        if (lane >= o) v += t;
    }
    if (lane == 31) wsum[wid] = v;
    __syncthreads();
    if (wid == 0) {
        int s = wsum[lane];
#pragma unroll
        for (int o = 1; o < 32; o <<= 1) {
            int t = __shfl_up_sync(0xFFFFFFFF, s, o);
            if (lane >= o) s += t;
        }
        wsum[lane] = s;
    }
    __syncthreads();
    int winc = (wid > 0) ? wsum[wid - 1] : 0;
    if (idx < NBINS) g_off[idx] = winc + (v - orig);
    if (tid == 1023) g_bsum[blockIdx.x] = winc + v;
}

__global__ void __launch_bounds__(512)
scan2_kernel()
{
    __shared__ int wsum[16];
    int tid  = threadIdx.x;
    int lane = tid & 31;
    int wid  = tid >> 5;
    int v = (tid < NBLK_SCAN) ? g_bsum[tid] : 0;
    int orig = v;
#pragma unroll
    for (int o = 1; o < 32; o <<= 1) {
        int t = __shfl_up_sync(0xFFFFFFFF, v, o);
        if (lane >= o) v += t;
    }
    if (lane == 31) wsum[wid] = v;
    __syncthreads();
    if (wid == 0 && lane < 16) {
        int s = wsum[lane];
#pragma unroll
        for (int o = 1; o < 16; o <<= 1) {
            int t = __shfl_up_sync(0xFFFF, s, o);
            if (lane >= o) s += t;
        }
        wsum[lane] = s;
    }
    __syncthreads();
    int winc = (wid > 0) ? wsum[wid - 1] : 0;
    if (tid < NBLK_SCAN) g_bsum[tid] = winc + (v - orig);
}

__global__ void __launch_bounds__(1024)
scan3_kernel()
{
    int idx = blockIdx.x * 1024 + threadIdx.x;
    if (idx < NBINS) g_off[idx] += g_bsum[blockIdx.x];
    if (idx == 0) g_off[NBINS] = NEDGE;
}

__global__ void scatter_kernel(const int* __restrict__ ei, const int* __restrict__ et)
{
    int e = blockIdx.x * blockDim.x + threadIdx.x;
    if (e >= NEDGE) return;
    int src = ei[e];
    int dst = ei[NEDGE + e];
    int r   = et[e];
    int bin = dst * NREL + r;
    int pos = g_off[bin] + atomicAdd(&g_fill[bin], 1);
    g_elist[pos] = src;
}

// ---------------- persistent-A main GEMM -------------------------------------
// 782 CTAs x 512 threads. A (128x128 fp16) staged once; loop 18 col tiles of
// W with cp.async double-buffered B. Warp tiles 32x32 (4x4 warp grid).
// SMEM: A @0 (34816), B0 @34816, B1 @69632 -> 104448 B -> 2 CTAs/SM.
#define RSTRIDE 272
#define SA_SZ   (128 * RSTRIDE)

__global__ void __launch_bounds__(512, 2)
main_gemm_kernel(const __half* __restrict__ Ah,
                 const __half* __restrict__ W,
                 const float* __restrict__ bias,
                 __half* __restrict__ Cout, int M)
{
    extern __shared__ char smem[];
    uint32_t sb = smem_u32(smem);

    int tid  = threadIdx.x;
    int wid  = tid >> 5;
    int lane = tid & 31;
    int rowBase = blockIdx.x * 128;

    // ---- stage A once ----
    for (int i = tid; i < 128 * 16; i += 512) {
        int row = i >> 4, ch = i & 15;
        int grow = rowBase + row;
        uint4 v = make_uint4(0, 0, 0, 0);
        if (grow < M)
            v = *(const uint4*)(Ah + (size_t)grow * DIM + ch * 8);
        *(uint4*)(smem + row * RSTRIDE + ch * 16) = v;
    }
    // ---- issue B(0) ----
    {
        uint32_t bufBase = sb + SA_SZ;
        for (int i = tid; i < 128 * 16; i += 512) {
            int row = i >> 4, ch = i & 15;
            cp_async16(bufBase + row * RSTRIDE + ch * 16,
                       W + (size_t)row * DIM + ch * 8);
        }
        cp_commit();
    }

    int mBase = (wid >> 2) * 32;
    int nBase = (wid & 3) * 32;

    uint32_t aAddr = sb + (uint32_t)(mBase + (lane & 15)) * RSTRIDE
                   + (uint32_t)((lane >> 4) << 3) * 2;
    uint32_t bLaneOff = (uint32_t)(nBase + (((lane >> 4) & 1) << 3) + (lane & 7)) * RSTRIDE
                      + (uint32_t)(((lane >> 3) & 1) << 3) * 2;

    for (int t = 0; t < NCT; ++t) {
        // prefetch next B tile
        if (t + 1 < NCT) {
            uint32_t bufBase = sb + SA_SZ + ((t + 1) & 1) * SA_SZ;
            const __half* wsrc = W + (size_t)(t + 1) * 128 * DIM;
            for (int i = tid; i < 128 * 16; i += 512) {
                int row = i >> 4, ch = i & 15;
                cp_async16(bufBase + row * RSTRIDE + ch * 16,
                           wsrc + (size_t)row * DIM + ch * 8);
            }
            cp_commit();
            cp_wait<1>();
        } else {
            cp_wait<0>();
        }
        __syncthreads();

        uint32_t bAddr = sb + SA_SZ + (t & 1) * SA_SZ + bLaneOff;

        float acc[2][4][4];
#pragma unroll
        for (int i = 0; i < 2; ++i)
#pragma unroll
            for (int j = 0; j < 4; ++j)
#pragma unroll
                for (int q = 0; q < 4; ++q) acc[i][j][q] = 0.0f;

#pragma unroll
        for (int ks = 0; ks < 8; ++ks) {
            uint32_t b[4][2];
#pragma unroll
            for (int jj = 0; jj < 2; ++jj) {
                uint32_t r[4];
                ldsm_x4(r, bAddr + jj * 16 * RSTRIDE + ks * 32);
                b[2 * jj][0] = r[0]; b[2 * jj][1] = r[1];
                b[2 * jj + 1][0] = r[2]; b[2 * jj + 1][1] = r[3];
            }
            uint32_t a[2][4];
#pragma unroll
            for (int i = 0; i < 2; ++i)
                ldsm_x4(a[i], aAddr + i * 16 * RSTRIDE + ks * 32);
#pragma unroll
            for (int i = 0; i < 2; ++i)
#pragma unroll
                for (int j = 0; j < 4; ++j)
                    mma16816(acc[i][j], a[i], b[j]);
        }

        // ---- epilogue: add bias, store fp16 cols [t*128, t*128+128) ----
        int colBase = t * 128;
#pragma unroll
        for (int i = 0; i < 2; ++i) {
            int row0 = rowBase + mBase + i * 16 + (lane >> 2);
#pragma unroll
            for (int h = 0; h < 2; ++h) {
                int grow = row0 + h * 8;
                if (grow >= M) continue;
                __half* crow = Cout + (size_t)grow * NCOLS + colBase;
#pragma unroll
                for (int j = 0; j < 4; ++j) {
                    int c = nBase + j * 8 + ((lane & 3) << 1);
                    float vx = acc[i][j][h * 2 + 0] + bias[colBase + c];
                    float vy = acc[i][j][h * 2 + 1] + bias[colBase + c + 1];
                    *(uint32_t*)(crow + c) =
                        pack2h(__float2half_rn(vx), __float2half_rn(vy));
                }
            }
        }
        __syncthreads();   // protect buffer (t&1) before reuse at t+2
    }
}

// ---------------- simple GEMM for the final projection -----------------------
__global__ void __launch_bounds__(512, 2)
proj_gemm_kernel(const __half* __restrict__ Ah,
                 const __half* __restrict__ W,
                 const float* __restrict__ bias,
                 float* __restrict__ Cout, int M)
{
    extern __shared__ char smem[];
    uint32_t sb = smem_u32(smem);

    int tid  = threadIdx.x;
    int wid  = tid >> 5;
    int lane = tid & 31;
    int rowBase = blockIdx.x * 128;
    const int colBase = NCOLS;   // linear1 block in g_Wh/bias

    const uint32_t sB = SA_SZ;

    for (int i = tid; i < 128 * 16; i += 512) {
        int row = i >> 4, ch = i & 15;
        int grow = rowBase + row;
        uint4 v = make_uint4(0, 0, 0, 0);
        if (grow < M)
            v = *(const uint4*)(Ah + (size_t)grow * DIM + ch * 8);
        *(uint4*)(smem + row * RSTRIDE + ch * 16) = v;
    }
    for (int i = tid; i < 128 * 16; i += 512) {
        int row = i >> 4, ch = i & 15;
        int gc = colBase + row;
        *(uint4*)(smem + sB + row * RSTRIDE + ch * 16) =
            *(const uint4*)(W + (size_t)gc * DIM + ch * 8);
    }
    __syncthreads();

    int mBase = (wid >> 2) * 32;
    int nBase = (wid & 3) * 32;

    float acc[2][4][4];
#pragma unroll
    for (int i = 0; i < 2; ++i)
#pragma unroll
        for (int j = 0; j < 4; ++j)
#pragma unroll
            for (int q = 0; q < 4; ++q) acc[i][j][q] = 0.0f;

    uint32_t aAddr = sb + (uint32_t)(mBase + (lane & 15)) * RSTRIDE
                   + (uint32_t)((lane >> 4) << 3) * 2;
    uint32_t bAddr = sb + sB
                   + (uint32_t)(nBase + (((lane >> 4) & 1) << 3) + (lane & 7)) * RSTRIDE
                   + (uint32_t)(((lane >> 3) & 1) << 3) * 2;

#pragma unroll
    for (int ks = 0; ks < 8; ++ks) {
        uint32_t b[4][2];
#pragma unroll
        for (int jj = 0; jj < 2; ++jj) {
            uint32_t r[4];
            ldsm_x4(r, bAddr + jj * 16 * RSTRIDE + ks * 32);
            b[2 * jj][0] = r[0]; b[2 * jj][1] = r[1];
            b[2 * jj + 1][0] = r[2]; b[2 * jj + 1][1] = r[3];
        }
        uint32_t a[2][4];
#pragma unroll
        for (int i = 0; i < 2; ++i)
            ldsm_x4(a[i], aAddr + i * 16 * RSTRIDE + ks * 32);
#pragma unroll
        for (int i = 0; i < 2; ++i)
#pragma unroll
            for (int j = 0; j < 4; ++j)
                mma16816(acc[i][j], a[i], b[j]);
    }

#pragma unroll
    for (int i = 0; i < 2; ++i) {
        int row0 = rowBase + mBase + i * 16 + (lane >> 2);
#pragma unroll
        for (int h = 0; h < 2; ++h) {
            int grow = row0 + h * 8;
            if (grow >= M) continue;
            float* crow = Cout + (size_t)grow * 128;
#pragma unroll
            for (int j = 0; j < 4; ++j) {
                int c = nBase + j * 8 + ((lane & 3) << 1);
                float2 v2;
                v2.x = acc[i][j][h * 2 + 0] + bias[colBase + c];
                v2.y = acc[i][j][h * 2 + 1] + bias[colBase + c + 1];
                *(float2*)(crow + c) = v2;
            }
        }
    }
}

// ---------------- aggregation: one warp per dst, binned by relation ---------
__global__ void __launch_bounds__(256)
agg_kernel()
{
    int gwarp = (blockIdx.x * blockDim.x + threadIdx.x) >> 5;
    int lane  = threadIdx.x & 31;
    if (gwarp >= N_NODES) return;
    int d = gwarp;
    int j = lane << 2;   // 4 cols per lane

    const __half* base = &g_C[(size_t)d * NCOLS];

    __half2 l01 = *(const __half2*)(base + j);
    __half2 l23 = *(const __half2*)(base + j + 2);
    __half2 b01 = *(const __half2*)(base + 128 + j);
    __half2 b23 = *(const __half2*)(base + 128 + j + 2);
    __half2 s01 = *(const __half2*)(base + 256 + j);
    __half2 s23 = *(const __half2*)(base + 256 + j + 2);
    float2 lf0 = __half22float2(l01), lf1 = __half22float2(l23);
    float2 bf0 = __half22float2(b01), bf1 = __half22float2(b23);
    float2 gf0 = __half22float2(s01), gf1 = __half22float2(s23);
    float4 acc;
    acc.x = fmaxf(gf0.x * lf0.x + bf0.x, 0.0f);
    acc.y = fmaxf(gf0.y * lf0.y + bf0.y, 0.0f);
    acc.z = fmaxf(gf1.x * lf1.x + bf1.x, 0.0f);
    acc.w = fmaxf(gf1.y * lf1.y + bf1.y, 0.0f);

#pragma unroll
    for (int r = 0; r < NREL; ++r) {
        int begin = g_off[d * NREL + r];
        int end   = g_off[d * NREL + r + 1];
        if (begin == end) continue;
        const __half* db = base + 384 + r * 384 + 128;
        __half2 eb01 = *(const __half2*)(db + j);
        __half2 eb23 = *(const __half2*)(db + j + 2);
        __half2 eg01 = *(const __half2*)(db + 128 + j);
        __half2 eg23 = *(const __half2*)(db + 128 + j + 2);
        float2 ebf0 = __half22float2(eb01), ebf1 = __half22float2(eb23);
        float2 egf0 = __half22float2(eg01), egf1 = __half22float2(eg23);
        float inv = 1.0f / (float)(end - begin);
        float4 racc = make_float4(0.f, 0.f, 0.f, 0.f);
        const size_t xlOff = 384 + (size_t)r * 384;
        for (int e = begin; e < end; ++e) {
            int src = g_elist[e];
            const __half* cb = &g_C[(size_t)src * NCOLS + xlOff];
            __half2 x01 = *(const __half2*)(cb + j);
            __half2 x23 = *(const __half2*)(cb + j + 2);
            float2 xf0 = __half22float2(x01), xf1 = __half22float2(x23);
            racc.x += fmaxf(egf0.x * xf0.x + ebf0.x, 0.0f);
            racc.y += fmaxf(egf0.y * xf0.y + ebf0.y, 0.0f);
            racc.z += fmaxf(egf1.x * xf1.x + ebf1.x, 0.0f);
            racc.w += fmaxf(egf1.y * xf1.y + ebf1.y, 0.0f);
        }
        acc.x += racc.x * inv;
        acc.y += racc.y * inv;
        acc.z += racc.z * inv;
        acc.w += racc.w * inv;
    }

    const float kk = 0.70710678118654752f;
    acc.x = 0.5f * acc.x * (1.0f + erff(acc.x * kk));
    acc.y = 0.5f * acc.y * (1.0f + erff(acc.y * kk));
    acc.z = 0.5f * acc.z * (1.0f + erff(acc.z * kk));
    acc.w = 0.5f * acc.w * (1.0f + erff(acc.w * kk));
    uint2 hv;
    hv.x = pack2h(__float2half_rn(acc.x), __float2half_rn(acc.y));
    hv.y = pack2h(__float2half_rn(acc.z), __float2half_rn(acc.w));
    *reinterpret_cast<uint2*>(&g_xh[(size_t)d * DIM + j]) = hv;
}

// ---------------- launch ------------------------------------------------------
extern "C" void kernel_launch(void* const* d_in, const int* in_sizes, int n_in,
                              void* d_out, int out_size)
{
    const float* x           = (const float*)d_in[0];
    const int*   ei          = (const int*)d_in[1];
    const int*   et          = (const int*)d_in[2];
    const float* lin_skip_w  = (const float*)d_in[3];
    const float* film_skip_w = (const float*)d_in[4];
    const float* lins_w      = (const float*)d_in[5];
    const float* films_w     = (const float*)d_in[6];
    const float* films_b     = (const float*)d_in[7];
    const float* linear1_w   = (const float*)d_in[8];
    const float* linear1_b   = (const float*)d_in[9];
    float*       out         = (float*)d_out;

    void *pC, *pXh, *pWh, *pBias;
    cudaGetSymbolAddress(&pC,   g_C);
    cudaGetSymbolAddress(&pXh,  g_xh);
    cudaGetSymbolAddress(&pWh,  g_Wh);
    cudaGetSymbolAddress(&pBias, g_biasv);

    const int SMEM_MAIN = 3 * SA_SZ;   // 104448
    const int SMEM_PROJ = 2 * SA_SZ;   // 69632
    cudaFuncSetAttribute((const void*)main_gemm_kernel,
                         cudaFuncAttributeMaxDynamicSharedMemorySize, SMEM_MAIN);
    cudaFuncSetAttribute((const void*)proj_gemm_kernel,
                         cudaFuncAttributeMaxDynamicSharedMemorySize, SMEM_PROJ);

    // 1. prep: x -> fp16; pack W^T fp16 + bias (incl. linear1)
    split_x_kernel<<<(N_NODES * DIM + 255) / 256, 256>>>(x);
    pack_wt_kernel<<<(NCOLSW * DIM + 255) / 256, 256>>>(
        lin_skip_w, film_skip_w, lins_w, films_w, films_b, linear1_w, linear1_b);

    // 2. edge indexing: counts -> parallel scan -> (dst,rel)-sorted src list
    zero_kernel<<<(NBINS + 255) / 256, 256>>>();
    cnt_kernel<<<(NEDGE + 255) / 256, 256>>>(ei, et);
    scan1_kernel<<<NBLK_SCAN, 1024>>>();
    scan2_kernel<<<1, 512>>>();
    scan3_kernel<<<NBLK_SCAN, 1024>>>();
    scatter_kernel<<<(NEDGE + 255) / 256, 256>>>(ei, et);

    // 3. main GEMM (persistent A, cp.async double-buffered B)
    main_gemm_kernel<<<(N_NODES + 127) / 128, 512, SMEM_MAIN>>>(
        (const __half*)pXh, (const __half*)pWh, (const float*)pBias,
        (__half*)pC, N_NODES);

    // 4. aggregation (skip + messages + GELU), atomics-free -> g_xh fp16
    {
        int warps_per_block = 256 / 32;
        int blocks = (N_NODES + warps_per_block - 1) / warps_per_block;
        agg_kernel<<<blocks, 256>>>();
    }

    // 5. final projection: out = gelu(out) @ linear1_w + linear1_b (fp32 out)
    proj_gemm_kernel<<<(N_NODES + 127) / 128, 512, SMEM_PROJ>>>(
        (const __half*)pXh, (const __half*)pWh, (const float*)pBias,
        out, N_NODES);
}

// round 13
// speedup vs baseline: 3.2767x; 1.0402x over previous
#include <cuda_runtime.h>
#include <cuda_fp16.h>
#include <math.h>
#include <stdint.h>

// Problem constants (fixed shapes)
#define N_NODES 100000
#define DIM     128
#define NEDGE   600000
#define NREL    5
#define NCOLS   2304          // 128 lin_skip + 256 film_skip + 5*(128 lins + 256 films)
#define NCOLSW  2432          // + 128 cols for linear1_w (final projection)
#define NBINS   (N_NODES * NREL)
#define NBLK_SCAN ((NBINS + 1023) / 1024)   // 489
#define NCT     18            // column tiles in main GEMM

// ---------------- scratch (device globals; no allocation allowed) ----------
__device__ __half   g_C[(size_t)N_NODES * NCOLS]; // fused node-GEMM output (fp16)
__device__ __half   g_xh[(size_t)N_NODES * DIM];  // x fp16; later gelu(out) fp16
__device__ __half   g_Wh[(size_t)NCOLSW * DIM];   // W^T fp16: [c][k]
__device__ float    g_biasv[NCOLSW];              // packed bias
__device__ int      g_cnt[NBINS];                 // per (dst, rel) edge count
__device__ int      g_off[NBINS + 1];             // CSR offsets by (dst, rel)
__device__ int      g_fill[NBINS];                // scatter cursors
__device__ int      g_bsum[512];                  // scan block sums
__device__ int      g_elist[NEDGE];               // src ids, (dst,rel)-sorted

// ---------------- PTX helpers (base PTX only; no 'a' features) -------------
__device__ __forceinline__ uint32_t smem_u32(const void* p) {
    uint32_t a;
    asm("{ .reg .u64 t; cvta.to.shared.u64 t, %1; cvt.u32.u64 %0, t; }"
        : "=r"(a) : "l"(p));
    return a;
}
__device__ __forceinline__ void ldsm_x4(uint32_t (&r)[4], uint32_t addr) {
    asm volatile("ldmatrix.sync.aligned.m8n8.x4.shared.b16 {%0,%1,%2,%3}, [%4];"
                 : "=r"(r[0]), "=r"(r[1]), "=r"(r[2]), "=r"(r[3]) : "r"(addr));
}
__device__ __forceinline__ void mma16816(float (&d)[4], const uint32_t (&a)[4],
                                         const uint32_t (&b)[2]) {
    asm volatile(
        "mma.sync.aligned.m16n8k16.row.col.f32.f16.f16.f32 "
        "{%0,%1,%2,%3}, {%4,%5,%6,%7}, {%8,%9}, {%0,%1,%2,%3};"
        : "+f"(d[0]), "+f"(d[1]), "+f"(d[2]), "+f"(d[3])
        : "r"(a[0]), "r"(a[1]), "r"(a[2]), "r"(a[3]), "r"(b[0]), "r"(b[1]));
}
__device__ __forceinline__ uint32_t pack2h(__half a, __half b) {
    __half2 t = __halves2half2(a, b);
    return *reinterpret_cast<uint32_t*>(&t);
}
__device__ __forceinline__ void cp_async16(uint32_t dst, const void* src) {
    asm volatile("cp.async.cg.shared.global [%0], [%1], 16;"
                 :: "r"(dst), "l"(src) : "memory");
}
__device__ __forceinline__ void cp_commit() {
    asm volatile("cp.async.commit_group;" ::: "memory");
}
template <int N>
__device__ __forceinline__ void cp_wait() {
    asm volatile("cp.async.wait_group %0;" :: "n"(N) : "memory");
}

// ---------------- prep kernels ----------------------------------------------
__global__ void split_x_kernel(const float* __restrict__ x)
{
    int i = blockIdx.x * blockDim.x + threadIdx.x;
    if (i >= N_NODES * DIM) return;
    g_xh[i] = __float2half_rn(x[i]);
}

__global__ void pack_wt_kernel(const float* __restrict__ lin_skip_w,
                               const float* __restrict__ film_skip_w,
                               const float* __restrict__ lins_w,
                               const float* __restrict__ films_w,
                               const float* __restrict__ films_b,
                               const float* __restrict__ linear1_w,
                               const float* __restrict__ linear1_b)
{
    int idx = blockIdx.x * blockDim.x + threadIdx.x;   // over NCOLSW*128
    if (idx < NCOLSW * DIM) {
        int c = idx / DIM;
        int k = idx % DIM;
        float v;
        if (c < 128) {
            v = lin_skip_w[k * 128 + c];
        } else if (c < 384) {
            v = film_skip_w[k * 256 + (c - 128)];
        } else if (c < NCOLS) {
            int r  = (c - 384) / 384;
            int cc = (c - 384) % 384;
            if (cc < 128) v = lins_w[((size_t)r * 128 + k) * 128 + cc];
            else          v = films_w[((size_t)r * 128 + k) * 256 + (cc - 128)];
        } else {
            v = linear1_w[k * 128 + (c - NCOLS)];
        }
        g_Wh[idx] = __float2half_rn(v);
    }
    if (idx < NCOLSW) {
        float b = 0.0f;
        if (idx >= 384 && idx < NCOLS) {
            int r  = (idx - 384) / 384;
            int cc = (idx - 384) % 384;
            if (cc >= 128) b = films_b[r * 256 + (cc - 128)];
        } else if (idx >= NCOLS) {
            b = linear1_b[idx - NCOLS];
        }
        g_biasv[idx] = b;
    }
}

__global__ void zero_kernel()
{
    int i = blockIdx.x * blockDim.x + threadIdx.x;
    if (i < NBINS) { g_cnt[i] = 0; g_fill[i] = 0; }
}

__global__ void cnt_kernel(const int* __restrict__ ei, const int* __restrict__ et)
{
    int e = blockIdx.x * blockDim.x + threadIdx.x;
    if (e < NEDGE) {
        int dst = ei[NEDGE + e];
        int r   = et[e];
        atomicAdd(&g_cnt[dst * NREL + r], 1);
    }
}

// ---- 3-phase parallel exclusive scan over g_cnt ----
__global__ void __launch_bounds__(1024)
scan1_kernel()
{
    __shared__ int wsum[32];
    int tid  = threadIdx.x;
    int lane = tid & 31;
    int wid  = tid >> 5;
    int idx  = blockIdx.x * 1024 + tid;
    int v = (idx < NBINS) ? g_cnt[idx] : 0;
    int orig = v;
#pragma unroll
    for (int o = 1; o < 32; o <<= 1) {
        int t = __shfl_up_sync(0xFFFFFFFF, v, o);
        if (lane >= o) v += t;
    }
    if (lane == 31) wsum[wid] = v;
    __syncthreads();
    if (wid == 0) {
        int s = wsum[lane];
#pragma unroll
        for (int o = 1; o < 32; o <<= 1) {
            int t = __shfl_up_sync(0xFFFFFFFF, s, o);
            if (lane >= o) s += t;
        }
        wsum[lane] = s;
    }
    __syncthreads();
    int winc = (wid > 0) ? wsum[wid - 1] : 0;
    if (idx < NBINS) g_off[idx] = winc + (v - orig);
    if (tid == 1023) g_bsum[blockIdx.x] = winc + v;
}

__global__ void __launch_bounds__(512)
scan2_kernel()
{
    __shared__ int wsum[16];
    int tid  = threadIdx.x;
    int lane = tid & 31;
    int wid  = tid >> 5;
    int v = (tid < NBLK_SCAN) ? g_bsum[tid] : 0;
    int orig = v;
#pragma unroll
    for (int o = 1; o < 32; o <<= 1) {
        int t = __shfl_up_sync(0xFFFFFFFF, v, o);
        if (lane >= o) v += t;
    }
    if (lane == 31) wsum[wid] = v;
    __syncthreads();
    if (wid == 0 && lane < 16) {
        int s = wsum[lane];
#pragma unroll
        for (int o = 1; o < 16; o <<= 1) {
            int t = __shfl_up_sync(0xFFFF, s, o);
            if (lane >= o) s += t;
        }
        wsum[lane] = s;
    }
    __syncthreads();
    int winc = (wid > 0) ? wsum[wid - 1] : 0;
    if (tid < NBLK_SCAN) g_bsum[tid] = winc + (v - orig);
}

__global__ void __launch_bounds__(1024)
scan3_kernel()
{
    int idx = blockIdx.x * 1024 + threadIdx.x;
    if (idx < NBINS) g_off[idx] += g_bsum[blockIdx.x];
    if (idx == 0) g_off[NBINS] = NEDGE;
}

__global__ void scatter_kernel(const int* __restrict__ ei, const int* __restrict__ et)
{
    int e = blockIdx.x * blockDim.x + threadIdx.x;
    if (e >= NEDGE) return;
    int src = ei[e];
    int dst = ei[NEDGE + e];
    int r   = et[e];
    int bin = dst * NREL + r;
    int pos = g_off[bin] + atomicAdd(&g_fill[bin], 1);
    g_elist[pos] = src;
}

// ---------------- persistent-A main GEMM -------------------------------------
// 782 CTAs x 256 threads (8 warps, 64x32 warp tiles: 2m x 4n grid).
// A (128x128 fp16) staged once; loop 18 col tiles of W with cp.async
// double-buffered B. SMEM: A + 2xB = 104448 B -> 2 CTAs/SM (16 warps).
#define RSTRIDE 272
#define SA_SZ   (128 * RSTRIDE)

__global__ void __launch_bounds__(256, 2)
main_gemm_kernel(const __half* __restrict__ Ah,
                 const __half* __restrict__ W,
                 const float* __restrict__ bias,
                 __half* __restrict__ Cout, int M)
{
    extern __shared__ char smem[];
    uint32_t sb = smem_u32(smem);

    int tid  = threadIdx.x;
    int wid  = tid >> 5;
    int lane = tid & 31;
    int rowBase = blockIdx.x * 128;

    // ---- stage A once ----
    for (int i = tid; i < 128 * 16; i += 256) {
        int row = i >> 4, ch = i & 15;
        int grow = rowBase + row;
        uint4 v = make_uint4(0, 0, 0, 0);
        if (grow < M)
            v = *(const uint4*)(Ah + (size_t)grow * DIM + ch * 8);
        *(uint4*)(smem + row * RSTRIDE + ch * 16) = v;
    }
    // ---- issue B(0) ----
    {
        uint32_t bufBase = sb + SA_SZ;
        for (int i = tid; i < 128 * 16; i += 256) {
            int row = i >> 4, ch = i & 15;
            cp_async16(bufBase + row * RSTRIDE + ch * 16,
                       W + (size_t)row * DIM + ch * 8);
        }
        cp_commit();
    }

    // 8 warps: 2m x 4n grid of 64x32 warp tiles
    int mBase = (wid >> 2) * 64;
    int nBase = (wid & 3) * 32;

    uint32_t aAddr = sb + (uint32_t)(mBase + (lane & 15)) * RSTRIDE
                   + (uint32_t)((lane >> 4) << 3) * 2;
    uint32_t bLaneOff = (uint32_t)(nBase + (((lane >> 4) & 1) << 3) + (lane & 7)) * RSTRIDE
                      + (uint32_t)(((lane >> 3) & 1) << 3) * 2;

    for (int t = 0; t < NCT; ++t) {
        // prefetch next B tile
        if (t + 1 < NCT) {
            uint32_t bufBase = sb + SA_SZ + ((t + 1) & 1) * SA_SZ;
            const __half* wsrc = W + (size_t)(t + 1) * 128 * DIM;
            for (int i = tid; i < 128 * 16; i += 256) {
                int row = i >> 4, ch = i & 15;
                cp_async16(bufBase + row * RSTRIDE + ch * 16,
                           wsrc + (size_t)row * DIM + ch * 8);
            }
            cp_commit();
            cp_wait<1>();
        } else {
            cp_wait<0>();
        }
        __syncthreads();

        uint32_t bAddr = sb + SA_SZ + (t & 1) * SA_SZ + bLaneOff;

        float acc[4][4][4];
#pragma unroll
        for (int i = 0; i < 4; ++i)
#pragma unroll
            for (int j = 0; j < 4; ++j)
#pragma unroll
                for (int q = 0; q < 4; ++q) acc[i][j][q] = 0.0f;

#pragma unroll
        for (int ks = 0; ks < 8; ++ks) {
            uint32_t b[4][2];
#pragma unroll
            for (int jj = 0; jj < 2; ++jj) {
                uint32_t r[4];
                ldsm_x4(r, bAddr + jj * 16 * RSTRIDE + ks * 32);
                b[2 * jj][0] = r[0]; b[2 * jj][1] = r[1];
                b[2 * jj + 1][0] = r[2]; b[2 * jj + 1][1] = r[3];
            }
            uint32_t a[4][4];
#pragma unroll
            for (int i = 0; i < 4; ++i)
                ldsm_x4(a[i], aAddr + i * 16 * RSTRIDE + ks * 32);
#pragma unroll
            for (int i = 0; i < 4; ++i)
#pragma unroll
                for (int j = 0; j < 4; ++j)
                    mma16816(acc[i][j], a[i], b[j]);
        }

        // ---- epilogue: add bias, store fp16 cols [t*128, t*128+128) ----
        int colBase = t * 128;
#pragma unroll
        for (int i = 0; i < 4; ++i) {
            int row0 = rowBase + mBase + i * 16 + (lane >> 2);
#pragma unroll
            for (int h = 0; h < 2; ++h) {
                int grow = row0 + h * 8;
                if (grow >= M) continue;
                __half* crow = Cout + (size_t)grow * NCOLS + colBase;
#pragma unroll
                for (int j = 0; j < 4; ++j) {
                    int c = nBase + j * 8 + ((lane & 3) << 1);
                    float vx = acc[i][j][h * 2 + 0] + bias[colBase + c];
                    float vy = acc[i][j][h * 2 + 1] + bias[colBase + c + 1];
                    *(uint32_t*)(crow + c) =
                        pack2h(__float2half_rn(vx), __float2half_rn(vy));
                }
            }
        }
        __syncthreads();   // protect buffer (t&1) before prefetch reuses it
    }
}

// ---------------- simple GEMM for the final projection -----------------------
__global__ void __launch_bounds__(512, 2)
proj_gemm_kernel(const __half* __restrict__ Ah,
                 const __half* __restrict__ W,
                 const float* __restrict__ bias,
                 float* __restrict__ Cout, int M)
{
    extern __shared__ char smem[];
    uint32_t sb = smem_u32(smem);

    int tid  = threadIdx.x;
    int wid  = tid >> 5;
    int lane = tid & 31;
    int rowBase = blockIdx.x * 128;
    const int colBase = NCOLS;   // linear1 block in g_Wh/bias

    const uint32_t sB = SA_SZ;

    for (int i = tid; i < 128 * 16; i += 512) {
        int row = i >> 4, ch = i & 15;
        int grow = rowBase + row;
        uint4 v = make_uint4(0, 0, 0, 0);
        if (grow < M)
            v = *(const uint4*)(Ah + (size_t)grow * DIM + ch * 8);
        *(uint4*)(smem + row * RSTRIDE + ch * 16) = v;
    }
    for (int i = tid; i < 128 * 16; i += 512) {
        int row = i >> 4, ch = i & 15;
        int gc = colBase + row;
        *(uint4*)(smem + sB + row * RSTRIDE + ch * 16) =
            *(const uint4*)(W + (size_t)gc * DIM + ch * 8);
    }
    __syncthreads();

    int mBase = (wid >> 2) * 32;
    int nBase = (wid & 3) * 32;

    float acc[2][4][4];
#pragma unroll
    for (int i = 0; i < 2; ++i)
#pragma unroll
        for (int j = 0; j < 4; ++j)
#pragma unroll
            for (int q = 0; q < 4; ++q) acc[i][j][q] = 0.0f;

    uint32_t aAddr = sb + (uint32_t)(mBase + (lane & 15)) * RSTRIDE
                   + (uint32_t)((lane >> 4) << 3) * 2;
    uint32_t bAddr = sb + sB
                   + (uint32_t)(nBase + (((lane >> 4) & 1) << 3) + (lane & 7)) * RSTRIDE
                   + (uint32_t)(((lane >> 3) & 1) << 3) * 2;

#pragma unroll
    for (int ks = 0; ks < 8; ++ks) {
        uint32_t b[4][2];
#pragma unroll
        for (int jj = 0; jj < 2; ++jj) {
            uint32_t r[4];
            ldsm_x4(r, bAddr + jj * 16 * RSTRIDE + ks * 32);
            b[2 * jj][0] = r[0]; b[2 * jj][1] = r[1];
            b[2 * jj + 1][0] = r[2]; b[2 * jj + 1][1] = r[3];
        }
        uint32_t a[2][4];
#pragma unroll
        for (int i = 0; i < 2; ++i)
            ldsm_x4(a[i], aAddr + i * 16 * RSTRIDE + ks * 32);
#pragma unroll
        for (int i = 0; i < 2; ++i)
#pragma unroll
            for (int j = 0; j < 4; ++j)
                mma16816(acc[i][j], a[i], b[j]);
    }

#pragma unroll
    for (int i = 0; i < 2; ++i) {
        int row0 = rowBase + mBase + i * 16 + (lane >> 2);
#pragma unroll
        for (int h = 0; h < 2; ++h) {
            int grow = row0 + h * 8;
            if (grow >= M) continue;
            float* crow = Cout + (size_t)grow * 128;
#pragma unroll
            for (int j = 0; j < 4; ++j) {
                int c = nBase + j * 8 + ((lane & 3) << 1);
                float2 v2;
                v2.x = acc[i][j][h * 2 + 0] + bias[colBase + c];
                v2.y = acc[i][j][h * 2 + 1] + bias[colBase + c + 1];
                *(float2*)(crow + c) = v2;
            }
        }
    }
}

// ---------------- aggregation: one warp per dst, binned by relation ---------
__global__ void __launch_bounds__(256)
agg_kernel()
{
    int gwarp = (blockIdx.x * blockDim.x + threadIdx.x) >> 5;
    int lane  = threadIdx.x & 31;
    if (gwarp >= N_NODES) return;
    int d = gwarp;
    int j = lane << 2;   // 4 cols per lane

    const __half* base = &g_C[(size_t)d * NCOLS];

    __half2 l01 = *(const __half2*)(base + j);
    __half2 l23 = *(const __half2*)(base + j + 2);
    __half2 b01 = *(const __half2*)(base + 128 + j);
    __half2 b23 = *(const __half2*)(base + 128 + j + 2);
    __half2 s01 = *(const __half2*)(base + 256 + j);
    __half2 s23 = *(const __half2*)(base + 256 + j + 2);
    float2 lf0 = __half22float2(l01), lf1 = __half22float2(l23);
    float2 bf0 = __half22float2(b01), bf1 = __half22float2(b23);
    float2 gf0 = __half22float2(s01), gf1 = __half22float2(s23);
    float4 acc;
    acc.x = fmaxf(gf0.x * lf0.x + bf0.x, 0.0f);
    acc.y = fmaxf(gf0.y * lf0.y + bf0.y, 0.0f);
    acc.z = fmaxf(gf1.x * lf1.x + bf1.x, 0.0f);
    acc.w = fmaxf(gf1.y * lf1.y + bf1.y, 0.0f);

#pragma unroll
    for (int r = 0; r < NREL; ++r) {
        int begin = g_off[d * NREL + r];
        int end   = g_off[d * NREL + r + 1];
        if (begin == end) continue;
        const __half* db = base + 384 + r * 384 + 128;
        __half2 eb01 = *(const __half2*)(db + j);
        __half2 eb23 = *(const __half2*)(db + j + 2);
        __half2 eg01 = *(const __half2*)(db + 128 + j);
        __half2 eg23 = *(const __half2*)(db + 128 + j + 2);
        float2 ebf0 = __half22float2(eb01), ebf1 = __half22float2(eb23);
        float2 egf0 = __half22float2(eg01), egf1 = __half22float2(eg23);
        float inv = 1.0f / (float)(end - begin);
        float4 racc = make_float4(0.f, 0.f, 0.f, 0.f);
        const size_t xlOff = 384 + (size_t)r * 384;
        for (int e = begin; e < end; ++e) {
            int src = g_elist[e];
            const __half* cb = &g_C[(size_t)src * NCOLS + xlOff];
            __half2 x01 = *(const __half2*)(cb + j);
            __half2 x23 = *(const __half2*)(cb + j + 2);
            float2 xf0 = __half22float2(x01), xf1 = __half22float2(x23);
            racc.x += fmaxf(egf0.x * xf0.x + ebf0.x, 0.0f);
            racc.y += fmaxf(egf0.y * xf0.y + ebf0.y, 0.0f);
            racc.z += fmaxf(egf1.x * xf1.x + ebf1.x, 0.0f);
            racc.w += fmaxf(egf1.y * xf1.y + ebf1.y, 0.0f);
        }
        acc.x += racc.x * inv;
        acc.y += racc.y * inv;
        acc.z += racc.z * inv;
        acc.w += racc.w * inv;
    }

    const float kk = 0.70710678118654752f;
    acc.x = 0.5f * acc.x * (1.0f + erff(acc.x * kk));
    acc.y = 0.5f * acc.y * (1.0f + erff(acc.y * kk));
    acc.z = 0.5f * acc.z * (1.0f + erff(acc.z * kk));
    acc.w = 0.5f * acc.w * (1.0f + erff(acc.w * kk));
    uint2 hv;
    hv.x = pack2h(__float2half_rn(acc.x), __float2half_rn(acc.y));
    hv.y = pack2h(__float2half_rn(acc.z), __float2half_rn(acc.w));
    *reinterpret_cast<uint2*>(&g_xh[(size_t)d * DIM + j]) = hv;
}

// ---------------- launch ------------------------------------------------------
extern "C" void kernel_launch(void* const* d_in, const int* in_sizes, int n_in,
                              void* d_out, int out_size)
{
    const float* x           = (const float*)d_in[0];
    const int*   ei          = (const int*)d_in[1];
    const int*   et          = (const int*)d_in[2];
    const float* lin_skip_w  = (const float*)d_in[3];
    const float* film_skip_w = (const float*)d_in[4];
    const float* lins_w      = (const float*)d_in[5];
    const float* films_w     = (const float*)d_in[6];
    const float* films_b     = (const float*)d_in[7];
    const float* linear1_w   = (const float*)d_in[8];
    const float* linear1_b   = (const float*)d_in[9];
    float*       out         = (float*)d_out;

    void *pC, *pXh, *pWh, *pBias;
    cudaGetSymbolAddress(&pC,   g_C);
    cudaGetSymbolAddress(&pXh,  g_xh);
    cudaGetSymbolAddress(&pWh,  g_Wh);
    cudaGetSymbolAddress(&pBias, g_biasv);

    const int SMEM_MAIN = 3 * SA_SZ;   // 104448
    const int SMEM_PROJ = 2 * SA_SZ;   // 69632
    cudaFuncSetAttribute((const void*)main_gemm_kernel,
                         cudaFuncAttributeMaxDynamicSharedMemorySize, SMEM_MAIN);
    cudaFuncSetAttribute((const void*)proj_gemm_kernel,
                         cudaFuncAttributeMaxDynamicSharedMemorySize, SMEM_PROJ);

    // 1. prep: x -> fp16; pack W^T fp16 + bias (incl. linear1)
    split_x_kernel<<<(N_NODES * DIM + 255) / 256, 256>>>(x);
    pack_wt_kernel<<<(NCOLSW * DIM + 255) / 256, 256>>>(
        lin_skip_w, film_skip_w, lins_w, films_w, films_b, linear1_w, linear1_b);

    // 2. edge indexing: counts -> parallel scan -> (dst,rel)-sorted src list
    zero_kernel<<<(NBINS + 255) / 256, 256>>>();
    cnt_kernel<<<(NEDGE + 255) / 256, 256>>>(ei, et);
    scan1_kernel<<<NBLK_SCAN, 1024>>>();
    scan2_kernel<<<1, 512>>>();
    scan3_kernel<<<NBLK_SCAN, 1024>>>();
    scatter_kernel<<<(NEDGE + 255) / 256, 256>>>(ei, et);

    // 3. main GEMM (persistent A, cp.async double-buffered B, 64x32 warp tiles)
    main_gemm_kernel<<<(N_NODES + 127) / 128, 256, SMEM_MAIN>>>(
        (const __half*)pXh, (const __half*)pWh, (const float*)pBias,
        (__half*)pC, N_NODES);

    // 4. aggregation (skip + messages + GELU), atomics-free -> g_xh fp16
    {
        int warps_per_block = 256 / 32;
        int blocks = (N_NODES + warps_per_block - 1) / warps_per_block;
        agg_kernel<<<blocks, 256>>>();
    }

    // 5. final projection: out = gelu(out) @ linear1_w + linear1_b (fp32 out)
    proj_gemm_kernel<<<(N_NODES + 127) / 128, 512, SMEM_PROJ>>>(
        (const __half*)pXh, (const __half*)pWh, (const float*)pBias,
        out, N_NODES);
}